// round 4
// baseline (speedup 1.0000x reference)
#include <cuda_runtime.h>
#include <cstddef>

// ---------------------------------------------------------------------------
// EncoderStack: B=4, T=1024, D=1024, H=16, DK=64, DF=4096, fp32.
// Pipeline:
//   Q = x@Wq ; K = x@Wk ; V = x@Wv              (sgemm, EPI=0)
//   att = MHA(Q,K,V)                            (flash-style attention)
//   x1  = LN(x + att)                           (add_ln)
//   h1  = relu(x1@W1 + b1)                      (sgemm, EPI=1)
//   ff  = h1@W2 + b2                            (sgemm, EPI=2)
//   out = LN(x1 + ff)                           (add_ln)
// ---------------------------------------------------------------------------

#define Bsz 4
#define Tn  1024
#define Dn  1024
#define Hn  16
#define DKn 64
#define DFn 4096
#define Mrows (Bsz * Tn)   // 4096

// Scratch (device globals: allocation-free per harness rules)
__device__ float g_Q[Mrows * Dn];
__device__ float g_K[Mrows * Dn];
__device__ float g_V[Mrows * Dn];
__device__ float g_att[Mrows * Dn];
__device__ float g_x1[Mrows * Dn];
__device__ float g_h1[Mrows * DFn];
__device__ float g_ff[Mrows * Dn];

// ---------------------------------------------------------------------------
// SGEMM: C[M,N] = A[M,K] @ B[K,N]   (row-major, dims multiples of tile dims)
// EPI: 0 = none, 1 = +bias, relu, 2 = +bias
// 128x128 tile, BK=16, 256 threads, 8x8 per thread, 2-stage smem pipeline.
// ---------------------------------------------------------------------------
template <int EPI>
__global__ __launch_bounds__(256) void sgemm_kernel(
    const float* __restrict__ A, const float* __restrict__ B,
    const float* __restrict__ bias, float* __restrict__ C,
    int M, int N, int K)
{
    constexpr int BM = 128, BN = 128, BK = 16;
    __shared__ float As[2][BK][BM + 4];   // [buf][k][m], padded
    __shared__ float Bs[2][BK][BN];       // [buf][k][n]

    const int tid = threadIdx.x;
    const int tx = tid & 15;           // 0..15 -> N dir
    const int ty = tid >> 4;           // 0..15 -> M dir
    const int bm = blockIdx.y * BM;
    const int bn = blockIdx.x * BN;

    // Per-thread load coordinates (two float4 each for A and B per tile)
    const int ar = tid >> 2;           // 0..63   (second: ar+64)
    const int ac = (tid & 3) * 4;      // 0,4,8,12
    const int br = tid >> 5;           // 0..7    (second: br+8)
    const int bc = (tid & 31) * 4;     // 0..124

    float acc[8][8];
#pragma unroll
    for (int i = 0; i < 8; i++)
#pragma unroll
        for (int j = 0; j < 8; j++) acc[i][j] = 0.f;

    // ---- prologue: tile 0 -> buf 0
    {
        float4 a0 = *(const float4*)(A + (size_t)(bm + ar) * K + ac);
        float4 a1 = *(const float4*)(A + (size_t)(bm + ar + 64) * K + ac);
        float4 b0 = *(const float4*)(B + (size_t)(br) * N + bn + bc);
        float4 b1 = *(const float4*)(B + (size_t)(br + 8) * N + bn + bc);
        As[0][ac + 0][ar] = a0.x; As[0][ac + 1][ar] = a0.y;
        As[0][ac + 2][ar] = a0.z; As[0][ac + 3][ar] = a0.w;
        As[0][ac + 0][ar + 64] = a1.x; As[0][ac + 1][ar + 64] = a1.y;
        As[0][ac + 2][ar + 64] = a1.z; As[0][ac + 3][ar + 64] = a1.w;
        *(float4*)(&Bs[0][br][bc]) = b0;
        *(float4*)(&Bs[0][br + 8][bc]) = b1;
    }
    __syncthreads();

    int buf = 0;
    for (int k0 = 0; k0 < K; k0 += BK) {
        const bool has_next = (k0 + BK) < K;
        float4 a0, a1, b0, b1;
        if (has_next) {
            const int kn = k0 + BK;
            a0 = *(const float4*)(A + (size_t)(bm + ar) * K + kn + ac);
            a1 = *(const float4*)(A + (size_t)(bm + ar + 64) * K + kn + ac);
            b0 = *(const float4*)(B + (size_t)(kn + br) * N + bn + bc);
            b1 = *(const float4*)(B + (size_t)(kn + br + 8) * N + bn + bc);
        }

#pragma unroll
        for (int kk = 0; kk < BK; kk++) {
            float4 ra0 = *(const float4*)(&As[buf][kk][ty * 8]);
            float4 ra1 = *(const float4*)(&As[buf][kk][ty * 8 + 4]);
            float4 rb0 = *(const float4*)(&Bs[buf][kk][tx * 8]);
            float4 rb1 = *(const float4*)(&Bs[buf][kk][tx * 8 + 4]);
            float af[8] = {ra0.x, ra0.y, ra0.z, ra0.w, ra1.x, ra1.y, ra1.z, ra1.w};
            float bf[8] = {rb0.x, rb0.y, rb0.z, rb0.w, rb1.x, rb1.y, rb1.z, rb1.w};
#pragma unroll
            for (int i = 0; i < 8; i++)
#pragma unroll
                for (int j = 0; j < 8; j++) acc[i][j] += af[i] * bf[j];
        }

        if (has_next) {
            const int nb = buf ^ 1;
            As[nb][ac + 0][ar] = a0.x; As[nb][ac + 1][ar] = a0.y;
            As[nb][ac + 2][ar] = a0.z; As[nb][ac + 3][ar] = a0.w;
            As[nb][ac + 0][ar + 64] = a1.x; As[nb][ac + 1][ar + 64] = a1.y;
            As[nb][ac + 2][ar + 64] = a1.z; As[nb][ac + 3][ar + 64] = a1.w;
            *(float4*)(&Bs[nb][br][bc]) = b0;
            *(float4*)(&Bs[nb][br + 8][bc]) = b1;
        }
        __syncthreads();
        buf ^= 1;
    }

    // Epilogue
    float bb[8];
    if (EPI > 0) {
        float4 v0 = *(const float4*)(bias + bn + tx * 8);
        float4 v1 = *(const float4*)(bias + bn + tx * 8 + 4);
        bb[0] = v0.x; bb[1] = v0.y; bb[2] = v0.z; bb[3] = v0.w;
        bb[4] = v1.x; bb[5] = v1.y; bb[6] = v1.z; bb[7] = v1.w;
    }
#pragma unroll
    for (int i = 0; i < 8; i++) {
        float* row = C + (size_t)(bm + ty * 8 + i) * N + bn + tx * 8;
        float v[8];
#pragma unroll
        for (int j = 0; j < 8; j++) {
            float t = acc[i][j];
            if (EPI > 0) t += bb[j];
            if (EPI == 1) t = fmaxf(t, 0.f);
            v[j] = t;
        }
        *(float4*)(row)     = make_float4(v[0], v[1], v[2], v[3]);
        *(float4*)(row + 4) = make_float4(v[4], v[5], v[6], v[7]);
    }
}

// ---------------------------------------------------------------------------
// Flash-style attention. Q,K,V,O: (B*T, H*DK) row-major.
// grid: (T/64, B*H). block: 256 threads (16x16). Each CTA: 64 q-rows,
// streaming over T kv rows in blocks of 64, online softmax.
// ---------------------------------------------------------------------------
__global__ __launch_bounds__(256) void attn_kernel(
    const float* __restrict__ Qg, const float* __restrict__ Kg,
    const float* __restrict__ Vg, float* __restrict__ Og)
{
    extern __shared__ float sm[];
    float* Qs = sm;                // [64][65]
    float* Ks = sm + 64 * 65;      // [64][65]
    float* Vs = sm + 2 * 64 * 65;  // [64][65]
    float* Ps = sm + 3 * 64 * 65;  // [j=64][i=65]  (P transposed)

    const int tid = threadIdx.x;
    const int tx = tid & 15;       // kv/d direction
    const int ty = tid >> 4;       // q direction
    const int bh = blockIdx.y;
    const int b = bh >> 4;
    const int h = bh & 15;
    const int q0 = blockIdx.x * 64;
    const size_t rowbase = (size_t)b * Tn * Dn + (size_t)h * DKn;

    // Load + scale Q tile (64 rows x 64 cols)
    for (int i = tid; i < 64 * 16; i += 256) {
        int r = i >> 4;
        int c4 = (i & 15) * 4;
        float4 q = *(const float4*)(Qg + rowbase + (size_t)(q0 + r) * Dn + c4);
        Qs[r * 65 + c4 + 0] = q.x * 0.125f;
        Qs[r * 65 + c4 + 1] = q.y * 0.125f;
        Qs[r * 65 + c4 + 2] = q.z * 0.125f;
        Qs[r * 65 + c4 + 3] = q.w * 0.125f;
    }

    float m[4], l[4], o[4][4];
#pragma unroll
    for (int i = 0; i < 4; i++) {
        m[i] = -1e30f;
        l[i] = 0.f;
#pragma unroll
        for (int d = 0; d < 4; d++) o[i][d] = 0.f;
    }

    for (int kv0 = 0; kv0 < Tn; kv0 += 64) {
        // Load K,V tiles
        for (int i = tid; i < 64 * 16; i += 256) {
            int r = i >> 4;
            int c4 = (i & 15) * 4;
            size_t ga = rowbase + (size_t)(kv0 + r) * Dn + c4;
            float4 k = *(const float4*)(Kg + ga);
            float4 v = *(const float4*)(Vg + ga);
            Ks[r * 65 + c4 + 0] = k.x;
            Ks[r * 65 + c4 + 1] = k.y;
            Ks[r * 65 + c4 + 2] = k.z;
            Ks[r * 65 + c4 + 3] = k.w;
            Vs[r * 65 + c4 + 0] = v.x;
            Vs[r * 65 + c4 + 1] = v.y;
            Vs[r * 65 + c4 + 2] = v.z;
            Vs[r * 65 + c4 + 3] = v.w;
        }
        __syncthreads();

        // S = Qs @ Ks^T : thread tile 4(q) x 4(kv)
        float s[4][4];
#pragma unroll
        for (int i = 0; i < 4; i++)
#pragma unroll
            for (int j = 0; j < 4; j++) s[i][j] = 0.f;

        for (int d = 0; d < 64; d++) {
            float qv[4], kv[4];
#pragma unroll
            for (int i = 0; i < 4; i++) qv[i] = Qs[(ty * 4 + i) * 65 + d];
#pragma unroll
            for (int j = 0; j < 4; j++) kv[j] = Ks[(tx * 4 + j) * 65 + d];
#pragma unroll
            for (int i = 0; i < 4; i++)
#pragma unroll
                for (int j = 0; j < 4; j++) s[i][j] += qv[i] * kv[j];
        }

        // Online softmax per q-row (reduce across the 16 tx lanes, same half-warp)
#pragma unroll
        for (int i = 0; i < 4; i++) {
            float mm = fmaxf(fmaxf(s[i][0], s[i][1]), fmaxf(s[i][2], s[i][3]));
#pragma unroll
            for (int off = 8; off >= 1; off >>= 1)
                mm = fmaxf(mm, __shfl_xor_sync(0xffffffffu, mm, off));
            float mn = fmaxf(m[i], mm);
            float alpha = __expf(m[i] - mn);
            float ssum = 0.f;
#pragma unroll
            for (int j = 0; j < 4; j++) {
                s[i][j] = __expf(s[i][j] - mn);
                ssum += s[i][j];
            }
#pragma unroll
            for (int off = 8; off >= 1; off >>= 1)
                ssum += __shfl_xor_sync(0xffffffffu, ssum, off);
            l[i] = l[i] * alpha + ssum;
            m[i] = mn;
#pragma unroll
            for (int d = 0; d < 4; d++) o[i][d] *= alpha;
        }

        // Stash P transposed: Ps[j][i]
#pragma unroll
        for (int i = 0; i < 4; i++)
#pragma unroll
            for (int j = 0; j < 4; j++)
                Ps[(tx * 4 + j) * 65 + ty * 4 + i] = s[i][j];
        __syncthreads();

        // O += P @ V : thread tile 4(q) x 4(d)
        for (int j = 0; j < 64; j++) {
            float pv[4], vv[4];
#pragma unroll
            for (int i = 0; i < 4; i++) pv[i] = Ps[j * 65 + ty * 4 + i];
#pragma unroll
            for (int d = 0; d < 4; d++) vv[d] = Vs[j * 65 + tx * 4 + d];
#pragma unroll
            for (int i = 0; i < 4; i++)
#pragma unroll
                for (int d = 0; d < 4; d++) o[i][d] += pv[i] * vv[d];
        }
        __syncthreads();
    }

    // Write O (normalized)
#pragma unroll
    for (int i = 0; i < 4; i++) {
        float inv = 1.f / l[i];
        float* row = Og + rowbase + (size_t)(q0 + ty * 4 + i) * Dn + tx * 4;
#pragma unroll
        for (int d = 0; d < 4; d++) row[d] = o[i][d] * inv;
    }
}

// ---------------------------------------------------------------------------
// out[row,:] = LayerNorm(a[row,:] + b[row,:]) * g + beta    (D = 1024)
// grid = 4096, block = 256 (4 cols/thread)
// ---------------------------------------------------------------------------
__global__ __launch_bounds__(256) void add_ln_kernel(
    const float* __restrict__ A, const float* __restrict__ Bv,
    const float* __restrict__ g, const float* __restrict__ beta,
    float* __restrict__ out)
{
    const int row = blockIdx.x;
    const int tid = threadIdx.x;
    const float* a = A + (size_t)row * Dn;
    const float* b = Bv + (size_t)row * Dn;

    float v[4];
    float s = 0.f, s2 = 0.f;
#pragma unroll
    for (int i = 0; i < 4; i++) {
        int c = tid + i * 256;
        v[i] = a[c] + b[c];
        s += v[i];
        s2 += v[i] * v[i];
    }
#pragma unroll
    for (int off = 16; off >= 1; off >>= 1) {
        s += __shfl_xor_sync(0xffffffffu, s, off);
        s2 += __shfl_xor_sync(0xffffffffu, s2, off);
    }
    __shared__ float red[16];
    const int w = tid >> 5;
    if ((tid & 31) == 0) { red[w] = s; red[w + 8] = s2; }
    __syncthreads();
    float ts = 0.f, ts2 = 0.f;
#pragma unroll
    for (int i = 0; i < 8; i++) { ts += red[i]; ts2 += red[8 + i]; }
    const float mu = ts * (1.f / Dn);
    const float var = ts2 * (1.f / Dn) - mu * mu;
    const float r = rsqrtf(var + 1e-5f);
    float* orow = out + (size_t)row * Dn;
#pragma unroll
    for (int i = 0; i < 4; i++) {
        int c = tid + i * 256;
        orow[c] = (v[i] - mu) * r * g[c] + beta[c];
    }
}

// ---------------------------------------------------------------------------
extern "C" void kernel_launch(void* const* d_in, const int* in_sizes, int n_in,
                              void* d_out, int out_size)
{
    (void)in_sizes; (void)n_in; (void)out_size;
    const float* x    = (const float*)d_in[0];
    const float* Wq   = (const float*)d_in[1];
    const float* Wk   = (const float*)d_in[2];
    const float* Wv   = (const float*)d_in[3];
    const float* W1   = (const float*)d_in[4];
    const float* b1   = (const float*)d_in[5];
    const float* W2   = (const float*)d_in[6];
    const float* b2   = (const float*)d_in[7];
    const float* ln1g = (const float*)d_in[8];
    const float* ln1b = (const float*)d_in[9];
    const float* ln2g = (const float*)d_in[10];
    const float* ln2b = (const float*)d_in[11];
    float* out = (float*)d_out;

    float *Q, *K, *V, *att, *x1, *h1, *ff;
    cudaGetSymbolAddress((void**)&Q,   g_Q);
    cudaGetSymbolAddress((void**)&K,   g_K);
    cudaGetSymbolAddress((void**)&V,   g_V);
    cudaGetSymbolAddress((void**)&att, g_att);
    cudaGetSymbolAddress((void**)&x1,  g_x1);
    cudaGetSymbolAddress((void**)&h1,  g_h1);
    cudaGetSymbolAddress((void**)&ff,  g_ff);

    const int ATT_SMEM = 4 * 64 * 65 * (int)sizeof(float);  // 66560 B
    cudaFuncSetAttribute(attn_kernel, cudaFuncAttributeMaxDynamicSharedMemorySize, ATT_SMEM);

    // QKV projections: (4096x1024) @ (1024x1024)
    dim3 gQKV(Dn / 128, Mrows / 128);
    sgemm_kernel<0><<<gQKV, 256>>>(x, Wq, nullptr, Q, Mrows, Dn, Dn);
    sgemm_kernel<0><<<gQKV, 256>>>(x, Wk, nullptr, K, Mrows, Dn, Dn);
    sgemm_kernel<0><<<gQKV, 256>>>(x, Wv, nullptr, V, Mrows, Dn, Dn);

    // Attention
    attn_kernel<<<dim3(Tn / 64, Bsz * Hn), 256, ATT_SMEM>>>(Q, K, V, att);

    // x1 = LN(x + att)
    add_ln_kernel<<<Mrows, 256>>>(x, att, ln1g, ln1b, x1);

    // h1 = relu(x1 @ W1 + b1) : (4096x1024)@(1024x4096)
    sgemm_kernel<1><<<dim3(DFn / 128, Mrows / 128), 256>>>(x1, W1, b1, h1, Mrows, DFn, Dn);

    // ff = h1 @ W2 + b2 : (4096x4096)@(4096x1024)
    sgemm_kernel<2><<<dim3(Dn / 128, Mrows / 128), 256>>>(h1, W2, b2, ff, Mrows, Dn, DFn);

    // out = LN(x1 + ff)
    add_ln_kernel<<<Mrows, 256>>>(x1, ff, ln2g, ln2b, out);
}

// round 6
// speedup vs baseline: 1.8002x; 1.8002x over previous
#include <cuda_runtime.h>
#include <cuda_bf16.h>
#include <cstdint>
#include <cstddef>

// ---------------------------------------------------------------------------
// EncoderStack B=4 T=1024 D=1024 H=16 DK=64 DF=4096, fp32 in/out.
// GEMMs via mma.sync bf16 split-precision (hi|hi|lo)·(hi|lo|hi), K' = 3K.
// (tcgen05 is unavailable: harness PTX target is compute_100, not 100a.)
// ---------------------------------------------------------------------------
#define Bsz 4
#define Tn  1024
#define Dn  1024
#define Hn  16
#define DKn 64
#define DFn 4096
#define Mrows 4096
#define K3D (3 * Dn)     // 3072
#define K3F (3 * DFn)    // 12288
#define LDQKV 3072

// ---- scratch (device globals; allocation-free per harness rules) ----------
__device__ __nv_bfloat16 g_A3x [Mrows * K3D];      // x  split   [4096,3072]
__device__ __nv_bfloat16 g_B3qkv[3072 * K3D];      // Wq|Wk|Wv^T split
__device__ float         g_QKV [Mrows * 3072];     // Q|K|V fp32
__device__ float         g_att [Mrows * Dn];
__device__ float         g_x1  [Mrows * Dn];
__device__ __nv_bfloat16 g_A3x1[Mrows * K3D];      // x1 split
__device__ __nv_bfloat16 g_B3w1[DFn * K3D];        // W1^T split [4096,3072]
__device__ __nv_bfloat16 g_A3h [Mrows * K3F];      // relu(h1) split [4096,12288]
__device__ __nv_bfloat16 g_B3w2[Dn * K3F];         // W2^T split [1024,12288]
__device__ float         g_ff  [Mrows * Dn];

__device__ __forceinline__ uint32_t smem_u32(const void* p) {
    uint32_t a;
    asm("{ .reg .u64 t; cvta.to.shared.u64 t, %1; cvt.u32.u64 %0, t; }"
        : "=r"(a) : "l"(p));
    return a;
}

// ---------------------------------------------------------------------------
// Split-bf16 HMMA GEMM.  C[M,N] (128x128 tiles) = A'[M,K3] . B'[N,K3]^T
// A' row-major K-major bf16, B' row-major K-major bf16 (pre-transposed W).
// EPI 0: C fp32.  EPI 1: +bias, relu, write bf16 hi|hi|lo triple to C3.
// EPI 2: +bias, C fp32.
// 256 threads = 8 warps (2m x 4n), warp tile 64x32, BK=64,
// cp.async double-buffered smem with 16B-XOR swizzle, ldmatrix fragments.
// ---------------------------------------------------------------------------
template <int EPI>
__global__ __launch_bounds__(256) void gemm3_kernel(
    const __nv_bfloat16* __restrict__ A, const __nv_bfloat16* __restrict__ B,
    const float* __restrict__ bias,
    float* __restrict__ C, int ldc,
    __nv_bfloat16* __restrict__ C3, int c3stride, int c3seg,
    int KT)  // number of 64-wide K tiles
{
    extern __shared__ char dynsm[];
    char* base = (char*)(((uintptr_t)dynsm + 127) & ~(uintptr_t)127);
    __shared__ float s_bias[128];

    const int tid  = threadIdx.x;
    const int wid  = tid >> 5;
    const int lane = tid & 31;
    const int bm = blockIdx.y * 128;
    const int bn = blockIdx.x * 128;
    const int K3 = KT * 64;

    if (EPI > 0 && tid < 128) s_bias[tid] = bias[bn + tid];

    // smem stages: A tile 128x64 bf16 (16KB), B tile 128x64 bf16 (16KB)
    const uint32_t sA[2] = { smem_u32(base), smem_u32(base + 32768) };
    const uint32_t sB[2] = { sA[0] + 16384, sA[1] + 16384 };

    const __nv_bfloat16* Abase = A + (size_t)bm * K3;
    const __nv_bfloat16* Bbase = B + (size_t)bn * K3;

    // cp.async loader: row r (0..127) of 64 bf16 = 8 chunks of 16B,
    // chunk ch stored at (ch ^ (r&7)) to kill ldmatrix bank conflicts.
#define LOAD_STAGE(s, k0)                                                       \
    do {                                                                        \
        const __nv_bfloat16* Ag = Abase + (k0);                                 \
        const __nv_bfloat16* Bg = Bbase + (k0);                                 \
        _Pragma("unroll")                                                       \
        for (int i = 0; i < 4; i++) {                                           \
            int idx = tid + i * 256;                                            \
            int r = idx >> 3, ch = idx & 7;                                     \
            uint32_t off = (uint32_t)(r * 128 + ((ch ^ (r & 7)) << 4));         \
            asm volatile("cp.async.cg.shared.global [%0], [%1], 16;"            \
                :: "r"(sA[s] + off), "l"(Ag + (size_t)r * K3 + ch * 8)          \
                : "memory");                                                    \
            asm volatile("cp.async.cg.shared.global [%0], [%1], 16;"            \
                :: "r"(sB[s] + off), "l"(Bg + (size_t)r * K3 + ch * 8)          \
                : "memory");                                                    \
        }                                                                       \
        asm volatile("cp.async.commit_group;" ::: "memory");                    \
    } while (0)

    // warp tile origin
    const int wm = (wid >> 2) * 64;    // 0 / 64
    const int wn = (wid & 3) * 32;     // 0,32,64,96

    // ldmatrix per-thread row/chunk offsets (x4 matrix ordering)
    // A mats: (m0-7,k0) (m8-15,k0) (m0-7,k8) (m8-15,k8)
    const int a_roff = ((lane >> 3) & 1) * 8 + (lane & 7);
    const int a_koff = lane >> 4;              // chunk (+0/+1)
    // B mats: (n0-7,k0) (n0-7,k8) (n8-15,k0) (n8-15,k8)
    const int b_roff = ((lane >> 4) & 1) * 8 + (lane & 7);
    const int b_koff = (lane >> 3) & 1;

    float acc[4][4][4];
#pragma unroll
    for (int mt = 0; mt < 4; mt++)
#pragma unroll
        for (int nt = 0; nt < 4; nt++)
#pragma unroll
            for (int e = 0; e < 4; e++) acc[mt][nt][e] = 0.f;

    LOAD_STAGE(0, 0);

    for (int t = 0; t < KT; t++) {
        const int s = t & 1;
        if (t + 1 < KT) {
            LOAD_STAGE(s ^ 1, (t + 1) * 64);
            asm volatile("cp.async.wait_group 1;" ::: "memory");
        } else {
            asm volatile("cp.async.wait_group 0;" ::: "memory");
        }
        __syncthreads();

#pragma unroll
        for (int ks = 0; ks < 4; ks++) {           // 4 x K=16
            uint32_t af[4][4], bf2[2][4];
#pragma unroll
            for (int mt = 0; mt < 4; mt++) {
                int rA = wm + mt * 16 + a_roff;
                uint32_t addr = sA[s] + rA * 128 +
                                ((((ks << 1) + a_koff) ^ (rA & 7)) << 4);
                asm volatile(
                    "ldmatrix.sync.aligned.m8n8.x4.shared.b16 {%0,%1,%2,%3}, [%4];"
                    : "=r"(af[mt][0]), "=r"(af[mt][1]),
                      "=r"(af[mt][2]), "=r"(af[mt][3]) : "r"(addr));
            }
#pragma unroll
            for (int p = 0; p < 2; p++) {
                int rB = wn + p * 16 + b_roff;
                uint32_t addr = sB[s] + rB * 128 +
                                ((((ks << 1) + b_koff) ^ (rB & 7)) << 4);
                asm volatile(
                    "ldmatrix.sync.aligned.m8n8.x4.shared.b16 {%0,%1,%2,%3}, [%4];"
                    : "=r"(bf2[p][0]), "=r"(bf2[p][1]),
                      "=r"(bf2[p][2]), "=r"(bf2[p][3]) : "r"(addr));
            }
#pragma unroll
            for (int mt = 0; mt < 4; mt++)
#pragma unroll
                for (int nt = 0; nt < 4; nt++) {
                    uint32_t b0 = bf2[nt >> 1][(nt & 1) * 2];
                    uint32_t b1 = bf2[nt >> 1][(nt & 1) * 2 + 1];
                    float* c = acc[mt][nt];
                    asm volatile(
                        "mma.sync.aligned.m16n8k16.row.col.f32.bf16.bf16.f32 "
                        "{%0,%1,%2,%3}, {%4,%5,%6,%7}, {%8,%9}, {%0,%1,%2,%3};"
                        : "+f"(c[0]), "+f"(c[1]), "+f"(c[2]), "+f"(c[3])
                        : "r"(af[mt][0]), "r"(af[mt][1]),
                          "r"(af[mt][2]), "r"(af[mt][3]),
                          "r"(b0), "r"(b1));
                }
        }
        __syncthreads();
    }
#undef LOAD_STAGE

    // ---- epilogue: acc pairs (c0,c1)@row r0, (c2,c3)@row r0+8, cols col,col+1
    const int lr = lane >> 2;          // 0..7
    const int lc = (lane & 3) * 2;     // 0,2,4,6
#pragma unroll
    for (int mt = 0; mt < 4; mt++) {
#pragma unroll
        for (int nt = 0; nt < 4; nt++) {
            float* c = acc[mt][nt];
            const int tc   = wn + nt * 8 + lc;      // col within tile
            const int row0 = bm + wm + mt * 16 + lr;
            if (EPI == 1) {
                float h0a = fmaxf(c[0] + s_bias[tc],     0.f);
                float h1a = fmaxf(c[1] + s_bias[tc + 1], 0.f);
                float h0b = fmaxf(c[2] + s_bias[tc],     0.f);
                float h1b = fmaxf(c[3] + s_bias[tc + 1], 0.f);
                const int nn = bn + tc;
#pragma unroll
                for (int half = 0; half < 2; half++) {
                    float v0 = half ? h0b : h0a;
                    float v1 = half ? h1b : h1a;
                    __nv_bfloat16 hi0 = __float2bfloat16(v0);
                    __nv_bfloat16 hi1 = __float2bfloat16(v1);
                    __nv_bfloat16 lo0 = __float2bfloat16(v0 - __bfloat162float(hi0));
                    __nv_bfloat16 lo1 = __float2bfloat16(v1 - __bfloat162float(hi1));
                    __nv_bfloat162 hh; hh.x = hi0; hh.y = hi1;
                    __nv_bfloat162 ll; ll.x = lo0; ll.y = lo1;
                    __nv_bfloat16* o = C3 + (size_t)(row0 + half * 8) * c3stride;
                    *(__nv_bfloat162*)(o + nn)             = hh;
                    *(__nv_bfloat162*)(o + c3seg + nn)     = hh;
                    *(__nv_bfloat162*)(o + 2 * c3seg + nn) = ll;
                }
            } else {
                float b0v = (EPI == 2) ? s_bias[tc]     : 0.f;
                float b1v = (EPI == 2) ? s_bias[tc + 1] : 0.f;
                float2 v0 = make_float2(c[0] + b0v, c[1] + b1v);
                float2 v1 = make_float2(c[2] + b0v, c[3] + b1v);
                *(float2*)(C + (size_t)row0 * ldc + bn + tc)       = v0;
                *(float2*)(C + (size_t)(row0 + 8) * ldc + bn + tc) = v1;
            }
        }
    }
}

// ---------------------------------------------------------------------------
// Weight transpose + split:  W[K,N] fp32  ->  B3[N, 3K] bf16 = (hi | lo | hi)
// ---------------------------------------------------------------------------
__global__ __launch_bounds__(256) void wtrans3_kernel(
    const float* __restrict__ W, __nv_bfloat16* __restrict__ B3,
    int K, int N, int K3)
{
    __shared__ float t[32][33];
    const int n0 = blockIdx.x * 32, k0 = blockIdx.y * 32;
    const int tx = threadIdx.x & 31, ty = threadIdx.x >> 5;  // 32 x 8
#pragma unroll
    for (int i = 0; i < 4; i++)
        t[ty + 8 * i][tx] = W[(size_t)(k0 + ty + 8 * i) * N + n0 + tx];
    __syncthreads();
#pragma unroll
    for (int i = 0; i < 4; i++) {
        int n = n0 + ty + 8 * i;
        int k = k0 + tx;
        float v = t[tx][ty + 8 * i];
        __nv_bfloat16 hi = __float2bfloat16(v);
        __nv_bfloat16 lo = __float2bfloat16(v - __bfloat162float(hi));
        __nv_bfloat16* row = B3 + (size_t)n * K3;
        row[k] = hi; row[K + k] = lo; row[2 * K + k] = hi;
    }
}

// x fp32 [4096,1024] -> A3 bf16 [4096, 3072] = (hi | hi | lo)
__global__ __launch_bounds__(256) void conv3_kernel(
    const float* __restrict__ X, __nv_bfloat16* __restrict__ A3)
{
    const int m = blockIdx.x;
    const float* xr = X + (size_t)m * Dn;
    __nv_bfloat16* ar = A3 + (size_t)m * K3D;
#pragma unroll
    for (int i = 0; i < 4; i++) {
        int k = threadIdx.x + i * 256;
        float v = xr[k];
        __nv_bfloat16 hi = __float2bfloat16(v);
        __nv_bfloat16 lo = __float2bfloat16(v - __bfloat162float(hi));
        ar[k] = hi; ar[Dn + k] = hi; ar[2 * Dn + k] = lo;
    }
}

// ---------------------------------------------------------------------------
// Flash attention (validated R4 version; QKV row stride = 3072).
// ---------------------------------------------------------------------------
__global__ __launch_bounds__(256) void attn_kernel(
    const float* __restrict__ Qg, const float* __restrict__ Kg,
    const float* __restrict__ Vg, float* __restrict__ Og)
{
    extern __shared__ float sm[];
    float* Qs = sm;
    float* Ks = sm + 64 * 65;
    float* Vs = sm + 2 * 64 * 65;
    float* Ps = sm + 3 * 64 * 65;

    const int tid = threadIdx.x;
    const int tx = tid & 15;
    const int ty = tid >> 4;
    const int bh = blockIdx.y;
    const int b = bh >> 4;
    const int h = bh & 15;
    const int q0 = blockIdx.x * 64;
    const size_t rowbase = (size_t)b * Tn * LDQKV + (size_t)h * DKn;
    const size_t obase   = (size_t)b * Tn * Dn    + (size_t)h * DKn;

    for (int i = tid; i < 64 * 16; i += 256) {
        int r = i >> 4;
        int c4 = (i & 15) * 4;
        float4 q = *(const float4*)(Qg + rowbase + (size_t)(q0 + r) * LDQKV + c4);
        Qs[r * 65 + c4 + 0] = q.x * 0.125f;
        Qs[r * 65 + c4 + 1] = q.y * 0.125f;
        Qs[r * 65 + c4 + 2] = q.z * 0.125f;
        Qs[r * 65 + c4 + 3] = q.w * 0.125f;
    }

    float m[4], l[4], o[4][4];
#pragma unroll
    for (int i = 0; i < 4; i++) {
        m[i] = -1e30f; l[i] = 0.f;
#pragma unroll
        for (int d = 0; d < 4; d++) o[i][d] = 0.f;
    }

    for (int kv0 = 0; kv0 < Tn; kv0 += 64) {
        for (int i = tid; i < 64 * 16; i += 256) {
            int r = i >> 4;
            int c4 = (i & 15) * 4;
            size_t ga = rowbase + (size_t)(kv0 + r) * LDQKV + c4;
            float4 k = *(const float4*)(Kg + ga);
            float4 v = *(const float4*)(Vg + ga);
            Ks[r * 65 + c4 + 0] = k.x; Ks[r * 65 + c4 + 1] = k.y;
            Ks[r * 65 + c4 + 2] = k.z; Ks[r * 65 + c4 + 3] = k.w;
            Vs[r * 65 + c4 + 0] = v.x; Vs[r * 65 + c4 + 1] = v.y;
            Vs[r * 65 + c4 + 2] = v.z; Vs[r * 65 + c4 + 3] = v.w;
        }
        __syncthreads();

        float s[4][4];
#pragma unroll
        for (int i = 0; i < 4; i++)
#pragma unroll
            for (int j = 0; j < 4; j++) s[i][j] = 0.f;

        for (int d = 0; d < 64; d++) {
            float qv[4], kv[4];
#pragma unroll
            for (int i = 0; i < 4; i++) qv[i] = Qs[(ty * 4 + i) * 65 + d];
#pragma unroll
            for (int j = 0; j < 4; j++) kv[j] = Ks[(tx * 4 + j) * 65 + d];
#pragma unroll
            for (int i = 0; i < 4; i++)
#pragma unroll
                for (int j = 0; j < 4; j++) s[i][j] += qv[i] * kv[j];
        }

#pragma unroll
        for (int i = 0; i < 4; i++) {
            float mm = fmaxf(fmaxf(s[i][0], s[i][1]), fmaxf(s[i][2], s[i][3]));
#pragma unroll
            for (int off = 8; off >= 1; off >>= 1)
                mm = fmaxf(mm, __shfl_xor_sync(0xffffffffu, mm, off));
            float mn = fmaxf(m[i], mm);
            float alpha = __expf(m[i] - mn);
            float ssum = 0.f;
#pragma unroll
            for (int j = 0; j < 4; j++) {
                s[i][j] = __expf(s[i][j] - mn);
                ssum += s[i][j];
            }
#pragma unroll
            for (int off = 8; off >= 1; off >>= 1)
                ssum += __shfl_xor_sync(0xffffffffu, ssum, off);
            l[i] = l[i] * alpha + ssum;
            m[i] = mn;
#pragma unroll
            for (int d = 0; d < 4; d++) o[i][d] *= alpha;
        }

#pragma unroll
        for (int i = 0; i < 4; i++)
#pragma unroll
            for (int j = 0; j < 4; j++)
                Ps[(tx * 4 + j) * 65 + ty * 4 + i] = s[i][j];
        __syncthreads();

        for (int j = 0; j < 64; j++) {
            float pv[4], vv[4];
#pragma unroll
            for (int i = 0; i < 4; i++) pv[i] = Ps[j * 65 + ty * 4 + i];
#pragma unroll
            for (int d = 0; d < 4; d++) vv[d] = Vs[j * 65 + tx * 4 + d];
#pragma unroll
            for (int i = 0; i < 4; i++)
#pragma unroll
                for (int d = 0; d < 4; d++) o[i][d] += pv[i] * vv[d];
        }
        __syncthreads();
    }

#pragma unroll
    for (int i = 0; i < 4; i++) {
        float inv = 1.f / l[i];
        float* row = Og + obase + (size_t)(q0 + ty * 4 + i) * Dn + tx * 4;
#pragma unroll
        for (int d = 0; d < 4; d++) row[d] = o[i][d] * inv;
    }
}

// ---------------------------------------------------------------------------
// LayerNorm(a+b)*g+beta.  TRIPLE=1 additionally writes the bf16 hi|hi|lo split.
// ---------------------------------------------------------------------------
template <int TRIPLE>
__global__ __launch_bounds__(256) void add_ln_kernel(
    const float* __restrict__ A, const float* __restrict__ Bv,
    const float* __restrict__ g, const float* __restrict__ beta,
    float* __restrict__ out, __nv_bfloat16* __restrict__ A3)
{
    const int row = blockIdx.x;
    const int tid = threadIdx.x;
    const float* a = A + (size_t)row * Dn;
    const float* b = Bv + (size_t)row * Dn;

    float v[4];
    float s = 0.f, s2 = 0.f;
#pragma unroll
    for (int i = 0; i < 4; i++) {
        int c = tid + i * 256;
        v[i] = a[c] + b[c];
        s += v[i];
        s2 += v[i] * v[i];
    }
#pragma unroll
    for (int off = 16; off >= 1; off >>= 1) {
        s  += __shfl_xor_sync(0xffffffffu, s,  off);
        s2 += __shfl_xor_sync(0xffffffffu, s2, off);
    }
    __shared__ float red[16];
    const int w = tid >> 5;
    if ((tid & 31) == 0) { red[w] = s; red[w + 8] = s2; }
    __syncthreads();
    float ts = 0.f, ts2 = 0.f;
#pragma unroll
    for (int i = 0; i < 8; i++) { ts += red[i]; ts2 += red[8 + i]; }
    const float mu  = ts * (1.f / Dn);
    const float var = ts2 * (1.f / Dn) - mu * mu;
    const float r = rsqrtf(var + 1e-5f);
    float* orow = out + (size_t)row * Dn;
    __nv_bfloat16* a3 = TRIPLE ? (A3 + (size_t)row * K3D) : nullptr;
#pragma unroll
    for (int i = 0; i < 4; i++) {
        int c = tid + i * 256;
        float y = (v[i] - mu) * r * g[c] + beta[c];
        orow[c] = y;
        if (TRIPLE) {
            __nv_bfloat16 hi = __float2bfloat16(y);
            __nv_bfloat16 lo = __float2bfloat16(y - __bfloat162float(hi));
            a3[c] = hi; a3[Dn + c] = hi; a3[2 * Dn + c] = lo;
        }
    }
}

// ---------------------------------------------------------------------------
extern "C" void kernel_launch(void* const* d_in, const int* in_sizes, int n_in,
                              void* d_out, int out_size)
{
    (void)in_sizes; (void)n_in; (void)out_size;
    const float* x    = (const float*)d_in[0];
    const float* Wq   = (const float*)d_in[1];
    const float* Wk   = (const float*)d_in[2];
    const float* Wv   = (const float*)d_in[3];
    const float* W1   = (const float*)d_in[4];
    const float* b1   = (const float*)d_in[5];
    const float* W2   = (const float*)d_in[6];
    const float* b2   = (const float*)d_in[7];
    const float* ln1g = (const float*)d_in[8];
    const float* ln1b = (const float*)d_in[9];
    const float* ln2g = (const float*)d_in[10];
    const float* ln2b = (const float*)d_in[11];
    float* out = (float*)d_out;

    __nv_bfloat16 *A3x, *B3qkv, *A3x1, *B3w1, *A3h, *B3w2;
    float *QKV, *att, *x1, *ff;
    cudaGetSymbolAddress((void**)&A3x,   g_A3x);
    cudaGetSymbolAddress((void**)&B3qkv, g_B3qkv);
    cudaGetSymbolAddress((void**)&QKV,   g_QKV);
    cudaGetSymbolAddress((void**)&att,   g_att);
    cudaGetSymbolAddress((void**)&x1,    g_x1);
    cudaGetSymbolAddress((void**)&A3x1,  g_A3x1);
    cudaGetSymbolAddress((void**)&B3w1,  g_B3w1);
    cudaGetSymbolAddress((void**)&A3h,   g_A3h);
    cudaGetSymbolAddress((void**)&B3w2,  g_B3w2);
    cudaGetSymbolAddress((void**)&ff,    g_ff);

    const int GEMM_SMEM = 2 * 32768 + 128;                 // 2-stage A+B tiles
    const int ATT_SMEM  = 4 * 64 * 65 * (int)sizeof(float);
    cudaFuncSetAttribute(gemm3_kernel<0>, cudaFuncAttributeMaxDynamicSharedMemorySize, GEMM_SMEM);
    cudaFuncSetAttribute(gemm3_kernel<1>, cudaFuncAttributeMaxDynamicSharedMemorySize, GEMM_SMEM);
    cudaFuncSetAttribute(gemm3_kernel<2>, cudaFuncAttributeMaxDynamicSharedMemorySize, GEMM_SMEM);
    cudaFuncSetAttribute(attn_kernel,     cudaFuncAttributeMaxDynamicSharedMemorySize, ATT_SMEM);

    // ---- operand prep (split + transpose) ----
    conv3_kernel<<<Mrows, 256>>>(x, A3x);
    wtrans3_kernel<<<dim3(Dn / 32, Dn / 32), 256>>>(Wq, B3qkv,                      Dn,  Dn,  K3D);
    wtrans3_kernel<<<dim3(Dn / 32, Dn / 32), 256>>>(Wk, B3qkv + (size_t)1024 * K3D, Dn,  Dn,  K3D);
    wtrans3_kernel<<<dim3(Dn / 32, Dn / 32), 256>>>(Wv, B3qkv + (size_t)2048 * K3D, Dn,  Dn,  K3D);
    wtrans3_kernel<<<dim3(DFn / 32, Dn / 32), 256>>>(W1, B3w1,                      Dn,  DFn, K3D);
    wtrans3_kernel<<<dim3(Dn / 32, DFn / 32), 256>>>(W2, B3w2,                      DFn, Dn,  K3F);

    // ---- QKV = x @ [Wq|Wk|Wv]  (M=4096, N=3072, K3=3072) ----
    gemm3_kernel<0><<<dim3(3072 / 128, Mrows / 128), 256, GEMM_SMEM>>>(
        A3x, B3qkv, nullptr, QKV, 3072, nullptr, 0, 0, K3D / 64);

    // ---- attention ----
    attn_kernel<<<dim3(Tn / 64, Bsz * Hn), 256, ATT_SMEM>>>(
        QKV, QKV + 1024, QKV + 2048, att);

    // ---- x1 = LN(x + att)  (+ bf16 split for FFN1) ----
    add_ln_kernel<1><<<Mrows, 256>>>(x, att, ln1g, ln1b, x1, A3x1);

    // ---- h1 = relu(x1 @ W1 + b1) -> bf16 triple  (M=4096, N=4096, K3=3072) ----
    gemm3_kernel<1><<<dim3(DFn / 128, Mrows / 128), 256, GEMM_SMEM>>>(
        A3x1, B3w1, b1, nullptr, 0, A3h, K3F, DFn, K3D / 64);

    // ---- ff = h1 @ W2 + b2  (M=4096, N=1024, K3=12288) ----
    gemm3_kernel<2><<<dim3(Dn / 128, Mrows / 128), 256, GEMM_SMEM>>>(
        A3h, B3w2, b2, ff, Dn, nullptr, 0, 0, K3F / 64);

    // ---- out = LN(x1 + ff) ----
    add_ln_kernel<0><<<Mrows, 256>>>(x1, ff, ln2g, ln2b, out, nullptr);
}

// round 8
// speedup vs baseline: 2.5982x; 1.4433x over previous
#include <cuda_runtime.h>
#include <cuda_bf16.h>
#include <cstdint>
#include <cstddef>

// ---------------------------------------------------------------------------
// EncoderStack B=4 T=1024 D=1024 H=16 DK=64 DF=4096, fp32 in/out.
// GEMMs + attention via mma.sync bf16 split-precision (K' = 3K trick).
// ---------------------------------------------------------------------------
#define Bsz 4
#define Tn  1024
#define Dn  1024
#define Hn  16
#define DKn 64
#define DFn 4096
#define Mrows 4096
#define K3D (3 * Dn)     // 3072
#define K3F (3 * DFn)    // 12288
#define LDQKV 3072

// ---- scratch (device globals; allocation-free per harness rules) ----------
__device__ __nv_bfloat16 g_A3x [Mrows * K3D];
__device__ __nv_bfloat16 g_B3qkv[3072 * K3D];
__device__ float         g_QKV [Mrows * 3072];
__device__ float         g_att [Mrows * Dn];
__device__ float         g_x1  [Mrows * Dn];
__device__ __nv_bfloat16 g_A3x1[Mrows * K3D];
__device__ __nv_bfloat16 g_B3w1[DFn * K3D];
__device__ __nv_bfloat16 g_A3h [Mrows * K3F];
__device__ __nv_bfloat16 g_B3w2[Dn * K3F];
__device__ float         g_ff  [Mrows * Dn];

__device__ __forceinline__ uint32_t smem_u32(const void* p) {
    uint32_t a;
    asm("{ .reg .u64 t; cvta.to.shared.u64 t, %1; cvt.u32.u64 %0, t; }"
        : "=r"(a) : "l"(p));
    return a;
}
__device__ __forceinline__ void split2(float a, float b, uint32_t& hi, uint32_t& lo) {
    __nv_bfloat16 ha = __float2bfloat16(a), hb = __float2bfloat16(b);
    __nv_bfloat16 la = __float2bfloat16(a - __bfloat162float(ha));
    __nv_bfloat16 lb = __float2bfloat16(b - __bfloat162float(hb));
    __nv_bfloat162 H; H.x = ha; H.y = hb;
    __nv_bfloat162 L; L.x = la; L.y = lb;
    hi = *(uint32_t*)&H; lo = *(uint32_t*)&L;
}
__device__ __forceinline__ uint32_t pack_bf16(float a, float b) {
    __nv_bfloat162 t = __floats2bfloat162_rn(a, b);
    return *(uint32_t*)&t;
}

#define LDSM_X4(d, addr)                                                        \
    asm volatile("ldmatrix.sync.aligned.m8n8.x4.shared.b16 {%0,%1,%2,%3}, [%4];"\
        : "=r"((d)[0]), "=r"((d)[1]), "=r"((d)[2]), "=r"((d)[3]) : "r"(addr))
#define MMA16816(c, a0, a1, a2, a3, b0, b1)                                     \
    asm volatile("mma.sync.aligned.m16n8k16.row.col.f32.bf16.bf16.f32 "         \
        "{%0,%1,%2,%3}, {%4,%5,%6,%7}, {%8,%9}, {%0,%1,%2,%3};"                 \
        : "+f"((c)[0]), "+f"((c)[1]), "+f"((c)[2]), "+f"((c)[3])                \
        : "r"(a0), "r"(a1), "r"(a2), "r"(a3), "r"(b0), "r"(b1))

// ---------------------------------------------------------------------------
// Split-bf16 HMMA GEMM (unchanged from validated R6).
// ---------------------------------------------------------------------------
template <int EPI>
__global__ __launch_bounds__(256) void gemm3_kernel(
    const __nv_bfloat16* __restrict__ A, const __nv_bfloat16* __restrict__ B,
    const float* __restrict__ bias,
    float* __restrict__ C, int ldc,
    __nv_bfloat16* __restrict__ C3, int c3stride, int c3seg,
    int KT)
{
    extern __shared__ char dynsm[];
    char* base = (char*)(((uintptr_t)dynsm + 127) & ~(uintptr_t)127);
    __shared__ float s_bias[128];

    const int tid  = threadIdx.x;
    const int wid  = tid >> 5;
    const int lane = tid & 31;
    const int bm = blockIdx.y * 128;
    const int bn = blockIdx.x * 128;
    const int K3 = KT * 64;

    if (EPI > 0 && tid < 128) s_bias[tid] = bias[bn + tid];

    const uint32_t sA[2] = { smem_u32(base), smem_u32(base + 32768) };
    const uint32_t sB[2] = { sA[0] + 16384, sA[1] + 16384 };

    const __nv_bfloat16* Abase = A + (size_t)bm * K3;
    const __nv_bfloat16* Bbase = B + (size_t)bn * K3;

#define LOAD_STAGE(s, k0)                                                       \
    do {                                                                        \
        const __nv_bfloat16* Ag = Abase + (k0);                                 \
        const __nv_bfloat16* Bg = Bbase + (k0);                                 \
        _Pragma("unroll")                                                       \
        for (int i = 0; i < 4; i++) {                                           \
            int idx = tid + i * 256;                                            \
            int r = idx >> 3, ch = idx & 7;                                     \
            uint32_t off = (uint32_t)(r * 128 + ((ch ^ (r & 7)) << 4));         \
            asm volatile("cp.async.cg.shared.global [%0], [%1], 16;"            \
                :: "r"(sA[s] + off), "l"(Ag + (size_t)r * K3 + ch * 8)          \
                : "memory");                                                    \
            asm volatile("cp.async.cg.shared.global [%0], [%1], 16;"            \
                :: "r"(sB[s] + off), "l"(Bg + (size_t)r * K3 + ch * 8)          \
                : "memory");                                                    \
        }                                                                       \
        asm volatile("cp.async.commit_group;" ::: "memory");                    \
    } while (0)

    const int wm = (wid >> 2) * 64;
    const int wn = (wid & 3) * 32;
    const int a_roff = ((lane >> 3) & 1) * 8 + (lane & 7);
    const int a_koff = lane >> 4;
    const int b_roff = ((lane >> 4) & 1) * 8 + (lane & 7);
    const int b_koff = (lane >> 3) & 1;

    float acc[4][4][4];
#pragma unroll
    for (int mt = 0; mt < 4; mt++)
#pragma unroll
        for (int nt = 0; nt < 4; nt++)
#pragma unroll
            for (int e = 0; e < 4; e++) acc[mt][nt][e] = 0.f;

    LOAD_STAGE(0, 0);

    for (int t = 0; t < KT; t++) {
        const int s = t & 1;
        if (t + 1 < KT) {
            LOAD_STAGE(s ^ 1, (t + 1) * 64);
            asm volatile("cp.async.wait_group 1;" ::: "memory");
        } else {
            asm volatile("cp.async.wait_group 0;" ::: "memory");
        }
        __syncthreads();

#pragma unroll
        for (int ks = 0; ks < 4; ks++) {
            uint32_t af[4][4], bf2[2][4];
#pragma unroll
            for (int mt = 0; mt < 4; mt++) {
                int rA = wm + mt * 16 + a_roff;
                uint32_t addr = sA[s] + rA * 128 +
                                ((((ks << 1) + a_koff) ^ (rA & 7)) << 4);
                LDSM_X4(af[mt], addr);
            }
#pragma unroll
            for (int p = 0; p < 2; p++) {
                int rB = wn + p * 16 + b_roff;
                uint32_t addr = sB[s] + rB * 128 +
                                ((((ks << 1) + b_koff) ^ (rB & 7)) << 4);
                LDSM_X4(bf2[p], addr);
            }
#pragma unroll
            for (int mt = 0; mt < 4; mt++)
#pragma unroll
                for (int nt = 0; nt < 4; nt++) {
                    uint32_t b0 = bf2[nt >> 1][(nt & 1) * 2];
                    uint32_t b1 = bf2[nt >> 1][(nt & 1) * 2 + 1];
                    MMA16816(acc[mt][nt], af[mt][0], af[mt][1], af[mt][2], af[mt][3], b0, b1);
                }
        }
        __syncthreads();
    }
#undef LOAD_STAGE

    const int lr = lane >> 2;
    const int lc = (lane & 3) * 2;
#pragma unroll
    for (int mt = 0; mt < 4; mt++) {
#pragma unroll
        for (int nt = 0; nt < 4; nt++) {
            float* c = acc[mt][nt];
            const int tc   = wn + nt * 8 + lc;
            const int row0 = bm + wm + mt * 16 + lr;
            if (EPI == 1) {
                float h0a = fmaxf(c[0] + s_bias[tc],     0.f);
                float h1a = fmaxf(c[1] + s_bias[tc + 1], 0.f);
                float h0b = fmaxf(c[2] + s_bias[tc],     0.f);
                float h1b = fmaxf(c[3] + s_bias[tc + 1], 0.f);
                const int nn = bn + tc;
#pragma unroll
                for (int half = 0; half < 2; half++) {
                    float v0 = half ? h0b : h0a;
                    float v1 = half ? h1b : h1a;
                    uint32_t hh, ll;
                    split2(v0, v1, hh, ll);
                    __nv_bfloat16* o = C3 + (size_t)(row0 + half * 8) * c3stride;
                    *(uint32_t*)(o + nn)             = hh;
                    *(uint32_t*)(o + c3seg + nn)     = hh;
                    *(uint32_t*)(o + 2 * c3seg + nn) = ll;
                }
            } else {
                float b0v = (EPI == 2) ? s_bias[tc]     : 0.f;
                float b1v = (EPI == 2) ? s_bias[tc + 1] : 0.f;
                float2 v0 = make_float2(c[0] + b0v, c[1] + b1v);
                float2 v1 = make_float2(c[2] + b0v, c[3] + b1v);
                *(float2*)(C + (size_t)row0 * ldc + bn + tc)       = v0;
                *(float2*)(C + (size_t)(row0 + 8) * ldc + bn + tc) = v1;
            }
        }
    }
}

// ---------------------------------------------------------------------------
// HMMA flash attention.  One CTA = (b, h, 128 q-rows); 8 warps x m16.
// S = (Qhi|Qhi|Qlo).(Khi|Klo|Khi)^T  (K'=192), online softmax in regs,
// P (bf16, reg-remap) @ V (bf16 transposed in smem).
// smem: phase0 Qsplit 128x400B = 51200; loop: Ksplit 64x400B + Vt 64x144B.
// All C++ stores go through the generic pointer smp; u32 shared-space
// addresses are used ONLY for ldmatrix.
// ---------------------------------------------------------------------------
__global__ __launch_bounds__(256) void attn_mma_kernel(
    const float* __restrict__ Qg, const float* __restrict__ Kg,
    const float* __restrict__ Vg, float* __restrict__ Og)
{
    extern __shared__ char smraw[];
    char* smp = smraw;                         // generic pointer (stores)
    const uint32_t sQ = smem_u32(smraw);       // shared-space (ldmatrix)
    const uint32_t sK = sQ;
    const uint32_t sV = sQ + 25600;

    const int tid = threadIdx.x;
    const int wid = tid >> 5, lane = tid & 31;
    const int bh = blockIdx.y;
    const int b = bh >> 4, h = bh & 15;
    const int q0 = blockIdx.x * 128;
    const float* Qbase = Qg + (size_t)b * Tn * LDQKV + h * DKn;
    const float* Kbase = Kg + (size_t)b * Tn * LDQKV + h * DKn;
    const float* Vbase = Vg + (size_t)b * Tn * LDQKV + h * DKn;
    float* Obase = Og + (size_t)b * Tn * Dn + h * DKn;

    const int a_roff = ((lane >> 3) & 1) * 8 + (lane & 7);
    const int a_koff = lane >> 4;
    const int b_roff = ((lane >> 4) & 1) * 8 + (lane & 7);
    const int b_koff = (lane >> 3) & 1;

    // ---- stage Q split (scaled by 1/8): rows 128, layout (hi|hi|lo), 400B rows
#pragma unroll
    for (int i = 0; i < 8; i++) {
        int idx = tid + i * 256;
        int r = idx >> 4, c4 = (idx & 15) * 4;
        float4 q = *(const float4*)(Qbase + (size_t)(q0 + r) * LDQKV + c4);
        q.x *= 0.125f; q.y *= 0.125f; q.z *= 0.125f; q.w *= 0.125f;
        uint32_t h0, l0, h1, l1;
        split2(q.x, q.y, h0, l0);
        split2(q.z, q.w, h1, l1);
        char* row = smp + r * 400;
        *(uint2*)(row + c4 * 2)         = make_uint2(h0, h1);
        *(uint2*)(row + (64 + c4) * 2)  = make_uint2(h0, h1);
        *(uint2*)(row + (128 + c4) * 2) = make_uint2(l0, l1);
    }
    __syncthreads();

    // ---- Q fragments resident: 12 k-tiles (K'=192)
    uint32_t qf[12][4];
#pragma unroll
    for (int kt = 0; kt < 12; kt++) {
        uint32_t addr = sQ + (wid * 16 + a_roff) * 400 + (kt * 2 + a_koff) * 16;
        LDSM_X4(qf[kt], addr);
    }
    __syncthreads();

    float m0 = -1e30f, m1 = -1e30f, l0 = 0.f, l1 = 0.f;
    float of[8][4];
#pragma unroll
    for (int j = 0; j < 8; j++)
#pragma unroll
        for (int e = 0; e < 4; e++) of[j][e] = 0.f;

    for (int kv0 = 0; kv0 < Tn; kv0 += 64) {
        // ---- stage K split (hi|lo|hi) + V transposed bf16
#pragma unroll
        for (int i = 0; i < 4; i++) {
            int idx = tid + i * 256;
            int r = idx >> 4, c4 = (idx & 15) * 4;
            float4 k = *(const float4*)(Kbase + (size_t)(kv0 + r) * LDQKV + c4);
            uint32_t h0, lo0, h1, lo1;
            split2(k.x, k.y, h0, lo0);
            split2(k.z, k.w, h1, lo1);
            char* row = smp + r * 400;
            *(uint2*)(row + c4 * 2)         = make_uint2(h0, h1);
            *(uint2*)(row + (64 + c4) * 2)  = make_uint2(lo0, lo1);
            *(uint2*)(row + (128 + c4) * 2) = make_uint2(h0, h1);

            float4 v = *(const float4*)(Vbase + (size_t)(kv0 + r) * LDQKV + c4);
            char* vb = smp + 25600 + r * 2;
            *(__nv_bfloat16*)(vb + (c4 + 0) * 144) = __float2bfloat16(v.x);
            *(__nv_bfloat16*)(vb + (c4 + 1) * 144) = __float2bfloat16(v.y);
            *(__nv_bfloat16*)(vb + (c4 + 2) * 144) = __float2bfloat16(v.z);
            *(__nv_bfloat16*)(vb + (c4 + 3) * 144) = __float2bfloat16(v.w);
        }
        __syncthreads();

        // ---- S = Q' . K'^T : 8 n-tiles (kv64) x 12 k-tiles
        float sf[8][4];
#pragma unroll
        for (int nt = 0; nt < 8; nt++)
#pragma unroll
            for (int e = 0; e < 4; e++) sf[nt][e] = 0.f;

#pragma unroll
        for (int kt = 0; kt < 12; kt++) {
            uint32_t bf[4][4];
#pragma unroll
            for (int p = 0; p < 4; p++) {
                uint32_t addr = sK + (p * 16 + b_roff) * 400 + (kt * 2 + b_koff) * 16;
                LDSM_X4(bf[p], addr);
            }
#pragma unroll
            for (int nt = 0; nt < 8; nt++) {
                uint32_t bb0 = bf[nt >> 1][(nt & 1) * 2];
                uint32_t bb1 = bf[nt >> 1][(nt & 1) * 2 + 1];
                MMA16816(sf[nt], qf[kt][0], qf[kt][1], qf[kt][2], qf[kt][3], bb0, bb1);
            }
        }

        // ---- online softmax (rows r=lane>>2 and r+8; quad = same row)
        float mx0 = -1e30f, mx1 = -1e30f;
#pragma unroll
        for (int nt = 0; nt < 8; nt++) {
            mx0 = fmaxf(mx0, fmaxf(sf[nt][0], sf[nt][1]));
            mx1 = fmaxf(mx1, fmaxf(sf[nt][2], sf[nt][3]));
        }
        mx0 = fmaxf(mx0, __shfl_xor_sync(0xffffffffu, mx0, 1));
        mx0 = fmaxf(mx0, __shfl_xor_sync(0xffffffffu, mx0, 2));
        mx1 = fmaxf(mx1, __shfl_xor_sync(0xffffffffu, mx1, 1));
        mx1 = fmaxf(mx1, __shfl_xor_sync(0xffffffffu, mx1, 2));
        float mn0 = fmaxf(m0, mx0), mn1 = fmaxf(m1, mx1);
        float alpha0 = __expf(m0 - mn0), alpha1 = __expf(m1 - mn1);
        m0 = mn0; m1 = mn1;
        float sum0 = 0.f, sum1 = 0.f;
#pragma unroll
        for (int nt = 0; nt < 8; nt++) {
            sf[nt][0] = __expf(sf[nt][0] - mn0);
            sf[nt][1] = __expf(sf[nt][1] - mn0);
            sf[nt][2] = __expf(sf[nt][2] - mn1);
            sf[nt][3] = __expf(sf[nt][3] - mn1);
            sum0 += sf[nt][0] + sf[nt][1];
            sum1 += sf[nt][2] + sf[nt][3];
        }
        sum0 += __shfl_xor_sync(0xffffffffu, sum0, 1);
        sum0 += __shfl_xor_sync(0xffffffffu, sum0, 2);
        sum1 += __shfl_xor_sync(0xffffffffu, sum1, 1);
        sum1 += __shfl_xor_sync(0xffffffffu, sum1, 2);
        l0 = l0 * alpha0 + sum0;
        l1 = l1 * alpha1 + sum1;
#pragma unroll
        for (int j = 0; j < 8; j++) {
            of[j][0] *= alpha0; of[j][1] *= alpha0;
            of[j][2] *= alpha1; of[j][3] *= alpha1;
        }

        // ---- O += P @ V : accumulator->A-operand remap, V from smem
#pragma unroll
        for (int g = 0; g < 4; g++) {
            uint32_t a0 = pack_bf16(sf[2 * g][0],     sf[2 * g][1]);
            uint32_t a1 = pack_bf16(sf[2 * g][2],     sf[2 * g][3]);
            uint32_t a2 = pack_bf16(sf[2 * g + 1][0], sf[2 * g + 1][1]);
            uint32_t a3 = pack_bf16(sf[2 * g + 1][2], sf[2 * g + 1][3]);
            uint32_t vf[4][4];
#pragma unroll
            for (int p = 0; p < 4; p++) {
                uint32_t addr = sV + (p * 16 + b_roff) * 144 + (g * 2 + b_koff) * 16;
                LDSM_X4(vf[p], addr);
            }
#pragma unroll
            for (int j = 0; j < 8; j++) {
                uint32_t bb0 = vf[j >> 1][(j & 1) * 2];
                uint32_t bb1 = vf[j >> 1][(j & 1) * 2 + 1];
                MMA16816(of[j], a0, a1, a2, a3, bb0, bb1);
            }
        }
        __syncthreads();
    }

    // ---- write O (normalized), fp32
    const float inv0 = 1.f / l0, inv1 = 1.f / l1;
    const int r0 = q0 + wid * 16 + (lane >> 2);
    const int cc = (lane & 3) * 2;
#pragma unroll
    for (int j = 0; j < 8; j++) {
        *(float2*)(Obase + (size_t)r0 * Dn + j * 8 + cc) =
            make_float2(of[j][0] * inv0, of[j][1] * inv0);
        *(float2*)(Obase + (size_t)(r0 + 8) * Dn + j * 8 + cc) =
            make_float2(of[j][2] * inv1, of[j][3] * inv1);
    }
}

// ---------------------------------------------------------------------------
// Weight transpose + split:  W[K,N] fp32  ->  B3[N, 3K] bf16 = (hi | lo | hi)
// ---------------------------------------------------------------------------
__global__ __launch_bounds__(256) void wtrans3_kernel(
    const float* __restrict__ W, __nv_bfloat16* __restrict__ B3,
    int K, int N, int K3)
{
    __shared__ float t[32][33];
    const int n0 = blockIdx.x * 32, k0 = blockIdx.y * 32;
    const int tx = threadIdx.x & 31, ty = threadIdx.x >> 5;
#pragma unroll
    for (int i = 0; i < 4; i++)
        t[ty + 8 * i][tx] = W[(size_t)(k0 + ty + 8 * i) * N + n0 + tx];
    __syncthreads();
#pragma unroll
    for (int i = 0; i < 4; i++) {
        int n = n0 + ty + 8 * i;
        int k = k0 + tx;
        float v = t[tx][ty + 8 * i];
        __nv_bfloat16 hi = __float2bfloat16(v);
        __nv_bfloat16 lo = __float2bfloat16(v - __bfloat162float(hi));
        __nv_bfloat16* row = B3 + (size_t)n * K3;
        row[k] = hi; row[K + k] = lo; row[2 * K + k] = hi;
    }
}

// x fp32 [4096,1024] -> A3 bf16 [4096, 3072] = (hi | hi | lo)
__global__ __launch_bounds__(256) void conv3_kernel(
    const float* __restrict__ X, __nv_bfloat16* __restrict__ A3)
{
    const int m = blockIdx.x;
    const float* xr = X + (size_t)m * Dn;
    __nv_bfloat16* ar = A3 + (size_t)m * K3D;
#pragma unroll
    for (int i = 0; i < 4; i++) {
        int k = threadIdx.x + i * 256;
        float v = xr[k];
        __nv_bfloat16 hi = __float2bfloat16(v);
        __nv_bfloat16 lo = __float2bfloat16(v - __bfloat162float(hi));
        ar[k] = hi; ar[Dn + k] = hi; ar[2 * Dn + k] = lo;
    }
}

// ---------------------------------------------------------------------------
// LayerNorm(a+b)*g+beta.  TRIPLE=1 additionally writes the bf16 hi|hi|lo split.
// ---------------------------------------------------------------------------
template <int TRIPLE>
__global__ __launch_bounds__(256) void add_ln_kernel(
    const float* __restrict__ A, const float* __restrict__ Bv,
    const float* __restrict__ g, const float* __restrict__ beta,
    float* __restrict__ out, __nv_bfloat16* __restrict__ A3)
{
    const int row = blockIdx.x;
    const int tid = threadIdx.x;
    const float* a = A + (size_t)row * Dn;
    const float* b = Bv + (size_t)row * Dn;

    float v[4];
    float s = 0.f, s2 = 0.f;
#pragma unroll
    for (int i = 0; i < 4; i++) {
        int c = tid + i * 256;
        v[i] = a[c] + b[c];
        s += v[i];
        s2 += v[i] * v[i];
    }
#pragma unroll
    for (int off = 16; off >= 1; off >>= 1) {
        s  += __shfl_xor_sync(0xffffffffu, s,  off);
        s2 += __shfl_xor_sync(0xffffffffu, s2, off);
    }
    __shared__ float red[16];
    const int w = tid >> 5;
    if ((tid & 31) == 0) { red[w] = s; red[w + 8] = s2; }
    __syncthreads();
    float ts = 0.f, ts2 = 0.f;
#pragma unroll
    for (int i = 0; i < 8; i++) { ts += red[i]; ts2 += red[8 + i]; }
    const float mu  = ts * (1.f / Dn);
    const float var = ts2 * (1.f / Dn) - mu * mu;
    const float r = rsqrtf(var + 1e-5f);
    float* orow = out + (size_t)row * Dn;
    __nv_bfloat16* a3 = TRIPLE ? (A3 + (size_t)row * K3D) : nullptr;
#pragma unroll
    for (int i = 0; i < 4; i++) {
        int c = tid + i * 256;
        float y = (v[i] - mu) * r * g[c] + beta[c];
        orow[c] = y;
        if (TRIPLE) {
            __nv_bfloat16 hi = __float2bfloat16(y);
            __nv_bfloat16 lo = __float2bfloat16(y - __bfloat162float(hi));
            a3[c] = hi; a3[Dn + c] = hi; a3[2 * Dn + c] = lo;
        }
    }
}

// ---------------------------------------------------------------------------
extern "C" void kernel_launch(void* const* d_in, const int* in_sizes, int n_in,
                              void* d_out, int out_size)
{
    (void)in_sizes; (void)n_in; (void)out_size;
    const float* x    = (const float*)d_in[0];
    const float* Wq   = (const float*)d_in[1];
    const float* Wk   = (const float*)d_in[2];
    const float* Wv   = (const float*)d_in[3];
    const float* W1   = (const float*)d_in[4];
    const float* b1   = (const float*)d_in[5];
    const float* W2   = (const float*)d_in[6];
    const float* b2   = (const float*)d_in[7];
    const float* ln1g = (const float*)d_in[8];
    const float* ln1b = (const float*)d_in[9];
    const float* ln2g = (const float*)d_in[10];
    const float* ln2b = (const float*)d_in[11];
    float* out = (float*)d_out;

    __nv_bfloat16 *A3x, *B3qkv, *A3x1, *B3w1, *A3h, *B3w2;
    float *QKV, *att, *x1, *ff;
    cudaGetSymbolAddress((void**)&A3x,   g_A3x);
    cudaGetSymbolAddress((void**)&B3qkv, g_B3qkv);
    cudaGetSymbolAddress((void**)&QKV,   g_QKV);
    cudaGetSymbolAddress((void**)&att,   g_att);
    cudaGetSymbolAddress((void**)&x1,    g_x1);
    cudaGetSymbolAddress((void**)&A3x1,  g_A3x1);
    cudaGetSymbolAddress((void**)&B3w1,  g_B3w1);
    cudaGetSymbolAddress((void**)&A3h,   g_A3h);
    cudaGetSymbolAddress((void**)&B3w2,  g_B3w2);
    cudaGetSymbolAddress((void**)&ff,    g_ff);

    const int GEMM_SMEM = 2 * 32768 + 128;
    const int ATT_SMEM  = 51200;
    cudaFuncSetAttribute(gemm3_kernel<0>, cudaFuncAttributeMaxDynamicSharedMemorySize, GEMM_SMEM);
    cudaFuncSetAttribute(gemm3_kernel<1>, cudaFuncAttributeMaxDynamicSharedMemorySize, GEMM_SMEM);
    cudaFuncSetAttribute(gemm3_kernel<2>, cudaFuncAttributeMaxDynamicSharedMemorySize, GEMM_SMEM);
    cudaFuncSetAttribute(attn_mma_kernel, cudaFuncAttributeMaxDynamicSharedMemorySize, ATT_SMEM);

    // ---- operand prep (split + transpose) ----
    conv3_kernel<<<Mrows, 256>>>(x, A3x);
    wtrans3_kernel<<<dim3(Dn / 32, Dn / 32), 256>>>(Wq, B3qkv,                      Dn,  Dn,  K3D);
    wtrans3_kernel<<<dim3(Dn / 32, Dn / 32), 256>>>(Wk, B3qkv + (size_t)1024 * K3D, Dn,  Dn,  K3D);
    wtrans3_kernel<<<dim3(Dn / 32, Dn / 32), 256>>>(Wv, B3qkv + (size_t)2048 * K3D, Dn,  Dn,  K3D);
    wtrans3_kernel<<<dim3(DFn / 32, Dn / 32), 256>>>(W1, B3w1,                      Dn,  DFn, K3D);
    wtrans3_kernel<<<dim3(Dn / 32, DFn / 32), 256>>>(W2, B3w2,                      DFn, Dn,  K3F);

    // ---- QKV = x @ [Wq|Wk|Wv]  (M=4096, N=3072, K3=3072) ----
    gemm3_kernel<0><<<dim3(3072 / 128, Mrows / 128), 256, GEMM_SMEM>>>(
        A3x, B3qkv, nullptr, QKV, 3072, nullptr, 0, 0, K3D / 64);

    // ---- attention (HMMA) ----
    attn_mma_kernel<<<dim3(Tn / 128, Bsz * Hn), 256, ATT_SMEM>>>(
        QKV, QKV + 1024, QKV + 2048, att);

    // ---- x1 = LN(x + att)  (+ bf16 split for FFN1) ----
    add_ln_kernel<1><<<Mrows, 256>>>(x, att, ln1g, ln1b, x1, A3x1);

    // ---- h1 = relu(x1 @ W1 + b1) -> bf16 triple ----
    gemm3_kernel<1><<<dim3(DFn / 128, Mrows / 128), 256, GEMM_SMEM>>>(
        A3x1, B3w1, b1, nullptr, 0, A3h, K3F, DFn, K3D / 64);

    // ---- ff = h1 @ W2 + b2 ----
    gemm3_kernel<2><<<dim3(Dn / 128, Mrows / 128), 256, GEMM_SMEM>>>(
        A3h, B3w2, b2, ff, Dn, nullptr, 0, 0, K3F / 64);

    // ---- out = LN(x1 + ff) ----
    add_ln_kernel<0><<<Mrows, 256>>>(x1, ff, ln2g, ln2b, out, nullptr);
}

// round 9
// speedup vs baseline: 2.7627x; 1.0633x over previous
#include <cuda_runtime.h>
#include <cuda_bf16.h>
#include <cstdint>
#include <cstddef>

// ---------------------------------------------------------------------------
// EncoderStack B=4 T=1024 D=1024 H=16 DK=64 DF=4096, fp32 in/out.
// GEMMs + attention via mma.sync bf16 split-precision:
//   C = (Ahi|Ahi|Alo) . (Bhi|Blo|Bhi)^T  over K' = 3K, but operands stored
//   deduped as (hi|lo) [2K]; the loader maps k-tile -> segment.
// ---------------------------------------------------------------------------
#define Bsz 4
#define Tn  1024
#define Dn  1024
#define Hn  16
#define DKn 64
#define DFn 4096
#define Mrows 4096
#define LDQKV 3072

// ---- scratch (device globals; allocation-free per harness rules) ----------
__device__ __nv_bfloat16 g_A2x [Mrows * 2048];     // x  (hi|lo)
__device__ __nv_bfloat16 g_B2qkv[3072 * 2048];     // Wq|Wk|Wv^T (hi|lo)
__device__ float         g_QKV [Mrows * 3072];
__device__ float         g_att [Mrows * Dn];
__device__ float         g_x1  [Mrows * Dn];
__device__ __nv_bfloat16 g_A2x1[Mrows * 2048];     // x1 (hi|lo)
__device__ __nv_bfloat16 g_B2w1[DFn * 2048];       // W1^T (hi|lo)
__device__ __nv_bfloat16 g_A2h [Mrows * 8192];     // relu(h1) (hi|lo)
__device__ __nv_bfloat16 g_B2w2[Dn * 8192];        // W2^T (hi|lo)
__device__ float         g_ff  [Mrows * Dn];

__device__ __forceinline__ uint32_t smem_u32(const void* p) {
    uint32_t a;
    asm("{ .reg .u64 t; cvta.to.shared.u64 t, %1; cvt.u32.u64 %0, t; }"
        : "=r"(a) : "l"(p));
    return a;
}
__device__ __forceinline__ void split2(float a, float b, uint32_t& hi, uint32_t& lo) {
    __nv_bfloat16 ha = __float2bfloat16(a), hb = __float2bfloat16(b);
    __nv_bfloat16 la = __float2bfloat16(a - __bfloat162float(ha));
    __nv_bfloat16 lb = __float2bfloat16(b - __bfloat162float(hb));
    __nv_bfloat162 H; H.x = ha; H.y = hb;
    __nv_bfloat162 L; L.x = la; L.y = lb;
    hi = *(uint32_t*)&H; lo = *(uint32_t*)&L;
}
__device__ __forceinline__ uint32_t pack_bf16(float a, float b) {
    __nv_bfloat162 t = __floats2bfloat162_rn(a, b);
    return *(uint32_t*)&t;
}

#define LDSM_X4(d, addr)                                                        \
    asm volatile("ldmatrix.sync.aligned.m8n8.x4.shared.b16 {%0,%1,%2,%3}, [%4];"\
        : "=r"((d)[0]), "=r"((d)[1]), "=r"((d)[2]), "=r"((d)[3]) : "r"(addr))
#define MMA16816(c, a0, a1, a2, a3, b0, b1)                                     \
    asm volatile("mma.sync.aligned.m16n8k16.row.col.f32.bf16.bf16.f32 "         \
        "{%0,%1,%2,%3}, {%4,%5,%6,%7}, {%8,%9}, {%0,%1,%2,%3};"                 \
        : "+f"((c)[0]), "+f"((c)[1]), "+f"((c)[2]), "+f"((c)[3])                \
        : "r"(a0), "r"(a1), "r"(a2), "r"(a3), "r"(b0), "r"(b1))

// ---------------------------------------------------------------------------
// Split-bf16 HMMA GEMM, 3-stage cp.async pipeline.
// A,B stored (hi|lo), row stride 2*Ksz. k-tile t in [0, 3*KT0):
//   seg = t/KT0;  A segment pattern (hi,hi,lo);  B segment pattern (hi,lo,hi).
// EPI 0: C fp32.  EPI 1: +bias, relu, write (hi|lo) bf16 pair to C3.
// EPI 2: +bias, C fp32.
// ---------------------------------------------------------------------------
template <int EPI>
__global__ __launch_bounds__(256) void gemm3_kernel(
    const __nv_bfloat16* __restrict__ A, const __nv_bfloat16* __restrict__ B,
    const float* __restrict__ bias,
    float* __restrict__ C, int ldc,
    __nv_bfloat16* __restrict__ C3, int c3stride, int c3seg,
    int Ksz, int KT0)   // Ksz = K elements per segment; KT0 = Ksz/64
{
    extern __shared__ char dynsm[];
    char* base = (char*)(((uintptr_t)dynsm + 127) & ~(uintptr_t)127);
    __shared__ float s_bias[128];

    const int tid  = threadIdx.x;
    const int wid  = tid >> 5;
    const int lane = tid & 31;
    const int bm = blockIdx.y * 128;
    const int bn = blockIdx.x * 128;
    const int K2 = 2 * Ksz;
    const int KT = 3 * KT0;

    if (EPI > 0 && tid < 128) s_bias[tid] = bias[bn + tid];

    uint32_t sA[3], sB[3];
#pragma unroll
    for (int s = 0; s < 3; s++) {
        sA[s] = smem_u32(base + s * 32768);
        sB[s] = sA[s] + 16384;
    }

    const __nv_bfloat16* Abase = A + (size_t)bm * K2;
    const __nv_bfloat16* Bbase = B + (size_t)bn * K2;

    // issue cp.async for k-tile u into stage s (segment-mapped offsets)
#define LOAD_STAGE(s, u)                                                        \
    do {                                                                        \
        const int _seg = ((u) >= 2 * KT0) ? 2 : (((u) >= KT0) ? 1 : 0);         \
        const int _kin = (u) - _seg * KT0;                                      \
        const __nv_bfloat16* Ag = Abase + (size_t)((_seg == 2) ? Ksz : 0)       \
                                        + (size_t)_kin * 64;                    \
        const __nv_bfloat16* Bg = Bbase + (size_t)((_seg == 1) ? Ksz : 0)       \
                                        + (size_t)_kin * 64;                    \
        _Pragma("unroll")                                                       \
        for (int i = 0; i < 4; i++) {                                           \
            int idx = tid + i * 256;                                            \
            int r = idx >> 3, ch = idx & 7;                                     \
            uint32_t off = (uint32_t)(r * 128 + ((ch ^ (r & 7)) << 4));         \
            asm volatile("cp.async.cg.shared.global [%0], [%1], 16;"            \
                :: "r"(sA[s] + off), "l"(Ag + (size_t)r * K2 + ch * 8)          \
                : "memory");                                                    \
            asm volatile("cp.async.cg.shared.global [%0], [%1], 16;"            \
                :: "r"(sB[s] + off), "l"(Bg + (size_t)r * K2 + ch * 8)          \
                : "memory");                                                    \
        }                                                                       \
        asm volatile("cp.async.commit_group;" ::: "memory");                    \
    } while (0)

    const int wm = (wid >> 2) * 64;
    const int wn = (wid & 3) * 32;
    const int a_roff = ((lane >> 3) & 1) * 8 + (lane & 7);
    const int a_koff = lane >> 4;
    const int b_roff = ((lane >> 4) & 1) * 8 + (lane & 7);
    const int b_koff = (lane >> 3) & 1;

    float acc[4][4][4];
#pragma unroll
    for (int mt = 0; mt < 4; mt++)
#pragma unroll
        for (int nt = 0; nt < 4; nt++)
#pragma unroll
            for (int e = 0; e < 4; e++) acc[mt][nt][e] = 0.f;

    LOAD_STAGE(0, 0);
    LOAD_STAGE(1, 1);

    int sidx = 0;
    for (int t = 0; t < KT; t++) {
        if (t + 1 < KT) {
            asm volatile("cp.async.wait_group 1;" ::: "memory");
        } else {
            asm volatile("cp.async.wait_group 0;" ::: "memory");
        }
        __syncthreads();
        if (t + 2 < KT) {
            const int ns = (sidx + 2 >= 3) ? sidx - 1 : sidx + 2;
            LOAD_STAGE(ns, t + 2);
        }

        const uint32_t cA = sA[sidx], cB = sB[sidx];
#pragma unroll
        for (int ks = 0; ks < 4; ks++) {
            uint32_t af[4][4], bf2[2][4];
#pragma unroll
            for (int mt = 0; mt < 4; mt++) {
                int rA = wm + mt * 16 + a_roff;
                uint32_t addr = cA + rA * 128 +
                                ((((ks << 1) + a_koff) ^ (rA & 7)) << 4);
                LDSM_X4(af[mt], addr);
            }
#pragma unroll
            for (int p = 0; p < 2; p++) {
                int rB = wn + p * 16 + b_roff;
                uint32_t addr = cB + rB * 128 +
                                ((((ks << 1) + b_koff) ^ (rB & 7)) << 4);
                LDSM_X4(bf2[p], addr);
            }
#pragma unroll
            for (int mt = 0; mt < 4; mt++)
#pragma unroll
                for (int nt = 0; nt < 4; nt++) {
                    uint32_t b0 = bf2[nt >> 1][(nt & 1) * 2];
                    uint32_t b1 = bf2[nt >> 1][(nt & 1) * 2 + 1];
                    MMA16816(acc[mt][nt], af[mt][0], af[mt][1], af[mt][2], af[mt][3], b0, b1);
                }
        }
        __syncthreads();
        sidx = (sidx + 1 == 3) ? 0 : sidx + 1;
    }
#undef LOAD_STAGE

    const int lr = lane >> 2;
    const int lc = (lane & 3) * 2;
#pragma unroll
    for (int mt = 0; mt < 4; mt++) {
#pragma unroll
        for (int nt = 0; nt < 4; nt++) {
            float* c = acc[mt][nt];
            const int tc   = wn + nt * 8 + lc;
            const int row0 = bm + wm + mt * 16 + lr;
            if (EPI == 1) {
                float h0a = fmaxf(c[0] + s_bias[tc],     0.f);
                float h1a = fmaxf(c[1] + s_bias[tc + 1], 0.f);
                float h0b = fmaxf(c[2] + s_bias[tc],     0.f);
                float h1b = fmaxf(c[3] + s_bias[tc + 1], 0.f);
                const int nn = bn + tc;
#pragma unroll
                for (int half = 0; half < 2; half++) {
                    float v0 = half ? h0b : h0a;
                    float v1 = half ? h1b : h1a;
                    uint32_t hh, ll;
                    split2(v0, v1, hh, ll);
                    __nv_bfloat16* o = C3 + (size_t)(row0 + half * 8) * c3stride;
                    *(uint32_t*)(o + nn)         = hh;
                    *(uint32_t*)(o + c3seg + nn) = ll;
                }
            } else {
                float b0v = (EPI == 2) ? s_bias[tc]     : 0.f;
                float b1v = (EPI == 2) ? s_bias[tc + 1] : 0.f;
                float2 v0 = make_float2(c[0] + b0v, c[1] + b1v);
                float2 v1 = make_float2(c[2] + b0v, c[3] + b1v);
                *(float2*)(C + (size_t)row0 * ldc + bn + tc)       = v0;
                *(float2*)(C + (size_t)(row0 + 8) * ldc + bn + tc) = v1;
            }
        }
    }
}

// ---------------------------------------------------------------------------
// HMMA flash attention (validated R8 version, unchanged).
// ---------------------------------------------------------------------------
__global__ __launch_bounds__(256) void attn_mma_kernel(
    const float* __restrict__ Qg, const float* __restrict__ Kg,
    const float* __restrict__ Vg, float* __restrict__ Og)
{
    extern __shared__ char smraw[];
    char* smp = smraw;
    const uint32_t sQ = smem_u32(smraw);
    const uint32_t sK = sQ;
    const uint32_t sV = sQ + 25600;

    const int tid = threadIdx.x;
    const int wid = tid >> 5, lane = tid & 31;
    const int bh = blockIdx.y;
    const int b = bh >> 4, h = bh & 15;
    const int q0 = blockIdx.x * 128;
    const float* Qbase = Qg + (size_t)b * Tn * LDQKV + h * DKn;
    const float* Kbase = Kg + (size_t)b * Tn * LDQKV + h * DKn;
    const float* Vbase = Vg + (size_t)b * Tn * LDQKV + h * DKn;
    float* Obase = Og + (size_t)b * Tn * Dn + h * DKn;

    const int a_roff = ((lane >> 3) & 1) * 8 + (lane & 7);
    const int a_koff = lane >> 4;
    const int b_roff = ((lane >> 4) & 1) * 8 + (lane & 7);
    const int b_koff = (lane >> 3) & 1;

#pragma unroll
    for (int i = 0; i < 8; i++) {
        int idx = tid + i * 256;
        int r = idx >> 4, c4 = (idx & 15) * 4;
        float4 q = *(const float4*)(Qbase + (size_t)(q0 + r) * LDQKV + c4);
        q.x *= 0.125f; q.y *= 0.125f; q.z *= 0.125f; q.w *= 0.125f;
        uint32_t h0, l0, h1, l1;
        split2(q.x, q.y, h0, l0);
        split2(q.z, q.w, h1, l1);
        char* row = smp + r * 400;
        *(uint2*)(row + c4 * 2)         = make_uint2(h0, h1);
        *(uint2*)(row + (64 + c4) * 2)  = make_uint2(h0, h1);
        *(uint2*)(row + (128 + c4) * 2) = make_uint2(l0, l1);
    }
    __syncthreads();

    uint32_t qf[12][4];
#pragma unroll
    for (int kt = 0; kt < 12; kt++) {
        uint32_t addr = sQ + (wid * 16 + a_roff) * 400 + (kt * 2 + a_koff) * 16;
        LDSM_X4(qf[kt], addr);
    }
    __syncthreads();

    float m0 = -1e30f, m1 = -1e30f, l0 = 0.f, l1 = 0.f;
    float of[8][4];
#pragma unroll
    for (int j = 0; j < 8; j++)
#pragma unroll
        for (int e = 0; e < 4; e++) of[j][e] = 0.f;

    for (int kv0 = 0; kv0 < Tn; kv0 += 64) {
#pragma unroll
        for (int i = 0; i < 4; i++) {
            int idx = tid + i * 256;
            int r = idx >> 4, c4 = (idx & 15) * 4;
            float4 k = *(const float4*)(Kbase + (size_t)(kv0 + r) * LDQKV + c4);
            uint32_t h0, lo0, h1, lo1;
            split2(k.x, k.y, h0, lo0);
            split2(k.z, k.w, h1, lo1);
            char* row = smp + r * 400;
            *(uint2*)(row + c4 * 2)         = make_uint2(h0, h1);
            *(uint2*)(row + (64 + c4) * 2)  = make_uint2(lo0, lo1);
            *(uint2*)(row + (128 + c4) * 2) = make_uint2(h0, h1);

            float4 v = *(const float4*)(Vbase + (size_t)(kv0 + r) * LDQKV + c4);
            char* vb = smp + 25600 + r * 2;
            *(__nv_bfloat16*)(vb + (c4 + 0) * 144) = __float2bfloat16(v.x);
            *(__nv_bfloat16*)(vb + (c4 + 1) * 144) = __float2bfloat16(v.y);
            *(__nv_bfloat16*)(vb + (c4 + 2) * 144) = __float2bfloat16(v.z);
            *(__nv_bfloat16*)(vb + (c4 + 3) * 144) = __float2bfloat16(v.w);
        }
        __syncthreads();

        float sf[8][4];
#pragma unroll
        for (int nt = 0; nt < 8; nt++)
#pragma unroll
            for (int e = 0; e < 4; e++) sf[nt][e] = 0.f;

#pragma unroll
        for (int kt = 0; kt < 12; kt++) {
            uint32_t bf[4][4];
#pragma unroll
            for (int p = 0; p < 4; p++) {
                uint32_t addr = sK + (p * 16 + b_roff) * 400 + (kt * 2 + b_koff) * 16;
                LDSM_X4(bf[p], addr);
            }
#pragma unroll
            for (int nt = 0; nt < 8; nt++) {
                uint32_t bb0 = bf[nt >> 1][(nt & 1) * 2];
                uint32_t bb1 = bf[nt >> 1][(nt & 1) * 2 + 1];
                MMA16816(sf[nt], qf[kt][0], qf[kt][1], qf[kt][2], qf[kt][3], bb0, bb1);
            }
        }

        float mx0 = -1e30f, mx1 = -1e30f;
#pragma unroll
        for (int nt = 0; nt < 8; nt++) {
            mx0 = fmaxf(mx0, fmaxf(sf[nt][0], sf[nt][1]));
            mx1 = fmaxf(mx1, fmaxf(sf[nt][2], sf[nt][3]));
        }
        mx0 = fmaxf(mx0, __shfl_xor_sync(0xffffffffu, mx0, 1));
        mx0 = fmaxf(mx0, __shfl_xor_sync(0xffffffffu, mx0, 2));
        mx1 = fmaxf(mx1, __shfl_xor_sync(0xffffffffu, mx1, 1));
        mx1 = fmaxf(mx1, __shfl_xor_sync(0xffffffffu, mx1, 2));
        float mn0 = fmaxf(m0, mx0), mn1 = fmaxf(m1, mx1);
        float alpha0 = __expf(m0 - mn0), alpha1 = __expf(m1 - mn1);
        m0 = mn0; m1 = mn1;
        float sum0 = 0.f, sum1 = 0.f;
#pragma unroll
        for (int nt = 0; nt < 8; nt++) {
            sf[nt][0] = __expf(sf[nt][0] - mn0);
            sf[nt][1] = __expf(sf[nt][1] - mn0);
            sf[nt][2] = __expf(sf[nt][2] - mn1);
            sf[nt][3] = __expf(sf[nt][3] - mn1);
            sum0 += sf[nt][0] + sf[nt][1];
            sum1 += sf[nt][2] + sf[nt][3];
        }
        sum0 += __shfl_xor_sync(0xffffffffu, sum0, 1);
        sum0 += __shfl_xor_sync(0xffffffffu, sum0, 2);
        sum1 += __shfl_xor_sync(0xffffffffu, sum1, 1);
        sum1 += __shfl_xor_sync(0xffffffffu, sum1, 2);
        l0 = l0 * alpha0 + sum0;
        l1 = l1 * alpha1 + sum1;
#pragma unroll
        for (int j = 0; j < 8; j++) {
            of[j][0] *= alpha0; of[j][1] *= alpha0;
            of[j][2] *= alpha1; of[j][3] *= alpha1;
        }

#pragma unroll
        for (int g = 0; g < 4; g++) {
            uint32_t a0 = pack_bf16(sf[2 * g][0],     sf[2 * g][1]);
            uint32_t a1 = pack_bf16(sf[2 * g][2],     sf[2 * g][3]);
            uint32_t a2 = pack_bf16(sf[2 * g + 1][0], sf[2 * g + 1][1]);
            uint32_t a3 = pack_bf16(sf[2 * g + 1][2], sf[2 * g + 1][3]);
            uint32_t vf[4][4];
#pragma unroll
            for (int p = 0; p < 4; p++) {
                uint32_t addr = sV + (p * 16 + b_roff) * 144 + (g * 2 + b_koff) * 16;
                LDSM_X4(vf[p], addr);
            }
#pragma unroll
            for (int j = 0; j < 8; j++) {
                uint32_t bb0 = vf[j >> 1][(j & 1) * 2];
                uint32_t bb1 = vf[j >> 1][(j & 1) * 2 + 1];
                MMA16816(of[j], a0, a1, a2, a3, bb0, bb1);
            }
        }
        __syncthreads();
    }

    const float inv0 = 1.f / l0, inv1 = 1.f / l1;
    const int r0 = q0 + wid * 16 + (lane >> 2);
    const int cc = (lane & 3) * 2;
#pragma unroll
    for (int j = 0; j < 8; j++) {
        *(float2*)(Obase + (size_t)r0 * Dn + j * 8 + cc) =
            make_float2(of[j][0] * inv0, of[j][1] * inv0);
        *(float2*)(Obase + (size_t)(r0 + 8) * Dn + j * 8 + cc) =
            make_float2(of[j][2] * inv1, of[j][3] * inv1);
    }
}

// ---------------------------------------------------------------------------
// Weight transpose + split:  W[K,N] fp32  ->  B2[N, 2K] bf16 = (hi | lo)
// ---------------------------------------------------------------------------
__global__ __launch_bounds__(256) void wtrans2_kernel(
    const float* __restrict__ W, __nv_bfloat16* __restrict__ B2,
    int K, int N, int K2)
{
    __shared__ float t[32][33];
    const int n0 = blockIdx.x * 32, k0 = blockIdx.y * 32;
    const int tx = threadIdx.x & 31, ty = threadIdx.x >> 5;
#pragma unroll
    for (int i = 0; i < 4; i++)
        t[ty + 8 * i][tx] = W[(size_t)(k0 + ty + 8 * i) * N + n0 + tx];
    __syncthreads();
#pragma unroll
    for (int i = 0; i < 4; i++) {
        int n = n0 + ty + 8 * i;
        int k = k0 + tx;
        float v = t[tx][ty + 8 * i];
        __nv_bfloat16 hi = __float2bfloat16(v);
        __nv_bfloat16 lo = __float2bfloat16(v - __bfloat162float(hi));
        __nv_bfloat16* row = B2 + (size_t)n * K2;
        row[k] = hi; row[K + k] = lo;
    }
}

// x fp32 [4096,1024] -> A2 bf16 [4096, 2048] = (hi | lo)
__global__ __launch_bounds__(256) void conv2_kernel(
    const float* __restrict__ X, __nv_bfloat16* __restrict__ A2)
{
    const int m = blockIdx.x;
    const float* xr = X + (size_t)m * Dn;
    __nv_bfloat16* ar = A2 + (size_t)m * 2048;
#pragma unroll
    for (int i = 0; i < 4; i++) {
        int k = threadIdx.x + i * 256;
        float v = xr[k];
        __nv_bfloat16 hi = __float2bfloat16(v);
        __nv_bfloat16 lo = __float2bfloat16(v - __bfloat162float(hi));
        ar[k] = hi; ar[Dn + k] = lo;
    }
}

// ---------------------------------------------------------------------------
// LayerNorm(a+b)*g+beta.  PAIR=1 also writes the (hi|lo) bf16 split.
// ---------------------------------------------------------------------------
template <int PAIR>
__global__ __launch_bounds__(256) void add_ln_kernel(
    const float* __restrict__ A, const float* __restrict__ Bv,
    const float* __restrict__ g, const float* __restrict__ beta,
    float* __restrict__ out, __nv_bfloat16* __restrict__ A2)
{
    const int row = blockIdx.x;
    const int tid = threadIdx.x;
    const float* a = A + (size_t)row * Dn;
    const float* b = Bv + (size_t)row * Dn;

    float v[4];
    float s = 0.f, s2 = 0.f;
#pragma unroll
    for (int i = 0; i < 4; i++) {
        int c = tid + i * 256;
        v[i] = a[c] + b[c];
        s += v[i];
        s2 += v[i] * v[i];
    }
#pragma unroll
    for (int off = 16; off >= 1; off >>= 1) {
        s  += __shfl_xor_sync(0xffffffffu, s,  off);
        s2 += __shfl_xor_sync(0xffffffffu, s2, off);
    }
    __shared__ float red[16];
    const int w = tid >> 5;
    if ((tid & 31) == 0) { red[w] = s; red[w + 8] = s2; }
    __syncthreads();
    float ts = 0.f, ts2 = 0.f;
#pragma unroll
    for (int i = 0; i < 8; i++) { ts += red[i]; ts2 += red[8 + i]; }
    const float mu  = ts * (1.f / Dn);
    const float var = ts2 * (1.f / Dn) - mu * mu;
    const float r = rsqrtf(var + 1e-5f);
    float* orow = out + (size_t)row * Dn;
    __nv_bfloat16* a2 = PAIR ? (A2 + (size_t)row * 2048) : nullptr;
#pragma unroll
    for (int i = 0; i < 4; i++) {
        int c = tid + i * 256;
        float y = (v[i] - mu) * r * g[c] + beta[c];
        orow[c] = y;
        if (PAIR) {
            __nv_bfloat16 hi = __float2bfloat16(y);
            __nv_bfloat16 lo = __float2bfloat16(y - __bfloat162float(hi));
            a2[c] = hi; a2[Dn + c] = lo;
        }
    }
}

// ---------------------------------------------------------------------------
extern "C" void kernel_launch(void* const* d_in, const int* in_sizes, int n_in,
                              void* d_out, int out_size)
{
    (void)in_sizes; (void)n_in; (void)out_size;
    const float* x    = (const float*)d_in[0];
    const float* Wq   = (const float*)d_in[1];
    const float* Wk   = (const float*)d_in[2];
    const float* Wv   = (const float*)d_in[3];
    const float* W1   = (const float*)d_in[4];
    const float* b1   = (const float*)d_in[5];
    const float* W2   = (const float*)d_in[6];
    const float* b2   = (const float*)d_in[7];
    const float* ln1g = (const float*)d_in[8];
    const float* ln1b = (const float*)d_in[9];
    const float* ln2g = (const float*)d_in[10];
    const float* ln2b = (const float*)d_in[11];
    float* out = (float*)d_out;

    __nv_bfloat16 *A2x, *B2qkv, *A2x1, *B2w1, *A2h, *B2w2;
    float *QKV, *att, *x1, *ff;
    cudaGetSymbolAddress((void**)&A2x,   g_A2x);
    cudaGetSymbolAddress((void**)&B2qkv, g_B2qkv);
    cudaGetSymbolAddress((void**)&QKV,   g_QKV);
    cudaGetSymbolAddress((void**)&att,   g_att);
    cudaGetSymbolAddress((void**)&x1,    g_x1);
    cudaGetSymbolAddress((void**)&A2x1,  g_A2x1);
    cudaGetSymbolAddress((void**)&B2w1,  g_B2w1);
    cudaGetSymbolAddress((void**)&A2h,   g_A2h);
    cudaGetSymbolAddress((void**)&B2w2,  g_B2w2);
    cudaGetSymbolAddress((void**)&ff,    g_ff);

    const int GEMM_SMEM = 3 * 32768 + 128;   // 3-stage A+B tiles
    const int ATT_SMEM  = 51200;
    cudaFuncSetAttribute(gemm3_kernel<0>, cudaFuncAttributeMaxDynamicSharedMemorySize, GEMM_SMEM);
    cudaFuncSetAttribute(gemm3_kernel<1>, cudaFuncAttributeMaxDynamicSharedMemorySize, GEMM_SMEM);
    cudaFuncSetAttribute(gemm3_kernel<2>, cudaFuncAttributeMaxDynamicSharedMemorySize, GEMM_SMEM);
    cudaFuncSetAttribute(attn_mma_kernel, cudaFuncAttributeMaxDynamicSharedMemorySize, ATT_SMEM);

    // ---- operand prep (split + transpose) ----
    conv2_kernel<<<Mrows, 256>>>(x, A2x);
    wtrans2_kernel<<<dim3(Dn / 32, Dn / 32), 256>>>(Wq, B2qkv,                      Dn,  Dn,  2048);
    wtrans2_kernel<<<dim3(Dn / 32, Dn / 32), 256>>>(Wk, B2qkv + (size_t)1024 * 2048, Dn,  Dn,  2048);
    wtrans2_kernel<<<dim3(Dn / 32, Dn / 32), 256>>>(Wv, B2qkv + (size_t)2048 * 2048, Dn,  Dn,  2048);
    wtrans2_kernel<<<dim3(DFn / 32, Dn / 32), 256>>>(W1, B2w1,                      Dn,  DFn, 2048);
    wtrans2_kernel<<<dim3(Dn / 32, DFn / 32), 256>>>(W2, B2w2,                      DFn, Dn,  8192);

    // ---- QKV = x @ [Wq|Wk|Wv]  (M=4096, N=3072, K=1024) ----
    gemm3_kernel<0><<<dim3(3072 / 128, Mrows / 128), 256, GEMM_SMEM>>>(
        A2x, B2qkv, nullptr, QKV, 3072, nullptr, 0, 0, Dn, Dn / 64);

    // ---- attention (HMMA) ----
    attn_mma_kernel<<<dim3(Tn / 128, Bsz * Hn), 256, ATT_SMEM>>>(
        QKV, QKV + 1024, QKV + 2048, att);

    // ---- x1 = LN(x + att)  (+ bf16 (hi|lo) split for FFN1) ----
    add_ln_kernel<1><<<Mrows, 256>>>(x, att, ln1g, ln1b, x1, A2x1);

    // ---- h1 = relu(x1 @ W1 + b1) -> bf16 (hi|lo)  (K=1024) ----
    gemm3_kernel<1><<<dim3(DFn / 128, Mrows / 128), 256, GEMM_SMEM>>>(
        A2x1, B2w1, b1, nullptr, 0, A2h, 8192, DFn, Dn, Dn / 64);

    // ---- ff = h1 @ W2 + b2  (K=4096) ----
    gemm3_kernel<2><<<dim3(Dn / 128, Mrows / 128), 256, GEMM_SMEM>>>(
        A2h, B2w2, b2, ff, Dn, nullptr, 0, 0, DFn, DFn / 64);

    // ---- out = LN(x1 + ff) ----
    add_ln_kernel<0><<<Mrows, 256>>>(x1, ff, ln2g, ln2b, out, nullptr);
}